// round 12
// baseline (speedup 1.0000x reference)
#include <cuda_runtime.h>
#include <cuda_bf16.h>
#include <cuda_fp16.h>
#include <math.h>
#include <stdint.h>

#define N_NODES 100000
#define NROWS_PAD 100096          // 782 * 128
#define N_EDGES 800000
#define LN_EPS 1e-5f

// ================= scratch (device globals; no allocation allowed) =================
__device__ float g_h[(size_t)N_NODES * 160];      // node state fp32
__device__ __half g_AB[(size_t)NROWS_PAD * 320];  // message A|B fp16 (L2-resident)
__device__ float g_msum[(size_t)N_NODES * 160];   // scatter-add accumulator
__device__ float g_tw[N_NODES];                   // gate
__device__ float g_cnt[N_NODES];                  // in-degree
__device__ float g_bias320[320];                  // [bm | 0]

// bf16 hi/lo pre-split GEMM A operands
__device__ __align__(16) __nv_bfloat16 g_ah[(size_t)NROWS_PAD * 128], g_al[(size_t)NROWS_PAD * 128];   // node_features
__device__ __align__(16) __nv_bfloat16 g_hh[(size_t)NROWS_PAD * 192], g_hl[(size_t)NROWS_PAD * 192];   // h (K=160 pad 192)
__device__ __align__(16) __nv_bfloat16 g_mh[(size_t)NROWS_PAD * 160], g_ml[(size_t)NROWS_PAD * 160];   // messages

// bf16 hi/lo split weights (zero-padded K)
__device__ __align__(16) __nv_bfloat16 g_weh[128 * 128], g_wel[128 * 128];   // encoder
__device__ __align__(16) __nv_bfloat16 g_wmh[320 * 192], g_wml[320 * 192];   // message
__device__ __align__(16) __nv_bfloat16 g_wuh[160 * 320], g_wul[160 * 320];   // update
__device__ __align__(16) __nv_bfloat16 g_woh[128 * 192], g_wol[128 * 192];   // output

// ================= helpers =================
__device__ __forceinline__ uint32_t smem_u32(const void* p) {
    uint32_t a;
    asm("{ .reg .u64 t; cvta.to.shared.u64 t, %1; cvt.u32.u64 %0, t; }" : "=r"(a) : "l"(p));
    return a;
}
#define SWZ128(o) ((o) ^ (((o) >> 3) & 0x70))

__device__ __forceinline__ void cpa16(uint32_t dst, const void* src) {
    asm volatile("cp.async.cg.shared.global [%0], [%1], 16;" :: "r"(dst), "l"(src));
}
#define CP_COMMIT() asm volatile("cp.async.commit_group;" ::: "memory")
#define CP_WAIT0()  asm volatile("cp.async.wait_group 0;" ::: "memory")

__device__ __forceinline__ void ldsm4(uint32_t* r, uint32_t addr) {
    asm volatile("ldmatrix.sync.aligned.m8n8.x4.shared.b16 {%0,%1,%2,%3}, [%4];"
        : "=r"(r[0]), "=r"(r[1]), "=r"(r[2]), "=r"(r[3]) : "r"(addr));
}
__device__ __forceinline__ void mma16816(float* d, const uint32_t* a, const uint32_t* b) {
    asm volatile("mma.sync.aligned.m16n8k16.row.col.f32.bf16.bf16.f32 "
        "{%0,%1,%2,%3},{%4,%5,%6,%7},{%8,%9},{%0,%1,%2,%3};"
        : "+f"(d[0]), "+f"(d[1]), "+f"(d[2]), "+f"(d[3])
        : "r"(a[0]), "r"(a[1]), "r"(a[2]), "r"(a[3]), "r"(b[0]), "r"(b[1]));
}
__device__ __forceinline__ void split2(float a, float b, uint32_t& hi, uint32_t& lo) {
    __nv_bfloat16 ha = __float2bfloat16(a), hb = __float2bfloat16(b);
    __nv_bfloat16 la = __float2bfloat16(a - __bfloat162float(ha));
    __nv_bfloat16 lb = __float2bfloat16(b - __bfloat162float(hb));
    hi = (uint32_t)__bfloat16_as_ushort(ha) | ((uint32_t)__bfloat16_as_ushort(hb) << 16);
    lo = (uint32_t)__bfloat16_as_ushort(la) | ((uint32_t)__bfloat16_as_ushort(lb) << 16);
}
__device__ __forceinline__ void st_split1(__nv_bfloat16* H, __nv_bfloat16* L, size_t idx, float v) {
    __nv_bfloat16 h = __float2bfloat16(v);
    H[idx] = h;
    L[idx] = __float2bfloat16(v - __bfloat162float(h));
}
__device__ __forceinline__ void st_split4(__nv_bfloat16* H, __nv_bfloat16* L, size_t idx, float4 v) {
    uint2 hp, lp;
    split2(v.x, v.y, hp.x, lp.x);
    split2(v.z, v.w, hp.y, lp.y);
    *(uint2*)(H + idx) = hp;
    *(uint2*)(L + idx) = lp;
}
__device__ __forceinline__ float wsum(float v) {
#pragma unroll
    for (int o = 16; o; o >>= 1) v += __shfl_xor_sync(0xffffffffu, v, o);
    return v;
}
__device__ __forceinline__ void red4(float* p, float4 v) {
    asm volatile("red.global.add.v4.f32 [%0], {%1,%2,%3,%4};"
                 :: "l"(p), "f"(v.x), "f"(v.y), "f"(v.z), "f"(v.w) : "memory");
}

// ================= tensor-core GEMM (mma.sync bf16x3 split), fused epilogues ======
// D[128, NT] tile = A[128, KPAD] @ W[NT, KPAD]^T.  A sources:
//   DUAL=false: Xh/Xl stride KPAD.
//   DUAL=true (update GEMM): cols<160 from Xh/Xl stride 192 (h split); cols>=160 from
//   X2h/X2l stride 160 (message split).
// EPI: 0 msg precompute -> g_AB fp16 + zero g_msum (n0==0 CTAs); 1 encoder; 2 update; 3 output
template<int NT, int KPAD, int EPI, bool DUAL>
__global__ __launch_bounds__(256, 2) void gemm_tc(
    const __nv_bfloat16* __restrict__ Xh, const __nv_bfloat16* __restrict__ Xl,
    const __nv_bfloat16* __restrict__ X2h, const __nv_bfloat16* __restrict__ X2l,
    const __nv_bfloat16* __restrict__ Wh, const __nv_bfloat16* __restrict__ Wl,
    const float* __restrict__ bias,
    float* __restrict__ Y, int ldy,
    const float* __restrict__ a0, const float* __restrict__ a1,
    const float* __restrict__ a2, const float* __restrict__ a3,
    const float* __restrict__ a4, const float* __restrict__ a5,
    const float* __restrict__ a6,
    float* __restrict__ w0)
{
    extern __shared__ __align__(16) char dsm[];
    char* base = (char*)((((uintptr_t)dsm) + 1023) & ~(uintptr_t)1023);
    const uint32_t sb = smem_u32(base);
    constexpr int A_HI = 0, A_LO = 16384, B_HI = 32768;
    constexpr int B_LO = 32768 + NT * 128;
    constexpr int NW = NT / 2;
    constexpr int NTILES = NW / 8;
    const int tid = threadIdx.x, wid = tid >> 5, lane = tid & 31;
    const int wm = wid & 3, wn = wid >> 2;
    const int bm0 = blockIdx.y * 128, n0 = blockIdx.x * NT;

    float acc[2][NTILES][4];
#pragma unroll
    for (int m = 0; m < 2; m++)
#pragma unroll
        for (int t = 0; t < NTILES; t++)
#pragma unroll
            for (int j = 0; j < 4; j++) acc[m][t][j] = 0.f;

    constexpr int NCHUNK = KPAD / 64;
    for (int ch = 0; ch < NCHUNK; ch++) {
        const int c0 = ch * 64;
#pragma unroll
        for (int s = tid; s < 128 * 8; s += 256) {
            int r = s >> 3, i = s & 7;
            int col = c0 + i * 8;
            uint32_t off = SWZ128((uint32_t)(r * 128 + i * 16));
            if (DUAL) {
                if (col < 160) {
                    cpa16(sb + A_HI + off, Xh + (size_t)(bm0 + r) * 192 + col);
                    cpa16(sb + A_LO + off, Xl + (size_t)(bm0 + r) * 192 + col);
                } else {
                    cpa16(sb + A_HI + off, X2h + (size_t)(bm0 + r) * 160 + col - 160);
                    cpa16(sb + A_LO + off, X2l + (size_t)(bm0 + r) * 160 + col - 160);
                }
            } else {
                cpa16(sb + A_HI + off, Xh + (size_t)(bm0 + r) * KPAD + col);
                cpa16(sb + A_LO + off, Xl + (size_t)(bm0 + r) * KPAD + col);
            }
        }
        for (int s = tid; s < NT * 8; s += 256) {
            int r = s >> 3, i = s & 7;
            uint32_t off = SWZ128((uint32_t)(r * 128 + i * 16));
            cpa16(sb + B_HI + off, Wh + (size_t)(n0 + r) * KPAD + c0 + i * 8);
            cpa16(sb + B_LO + off, Wl + (size_t)(n0 + r) * KPAD + c0 + i * 8);
        }
        CP_COMMIT();
        CP_WAIT0();
        __syncthreads();

#pragma unroll
        for (int ks = 0; ks < 4; ks++) {
            uint32_t ah[2][4], al[2][4];
            const int arow = wm * 32 + (lane & 15);
            const int akb = ks * 32 + ((lane >> 4) << 4);
            {
                uint32_t o0 = SWZ128((uint32_t)(arow * 128 + akb));
                ldsm4(ah[0], sb + A_HI + o0);
                ldsm4(al[0], sb + A_LO + o0);
                uint32_t o1 = SWZ128((uint32_t)((arow + 16) * 128 + akb));
                ldsm4(ah[1], sb + A_HI + o1);
                ldsm4(al[1], sb + A_LO + o1);
            }
            const int q = lane >> 3;
            const int browb = wn * NW + ((q >> 1) << 3) + (lane & 7);
            const int bkb = ks * 32 + (q & 1) * 16;
#pragma unroll
            for (int nt = 0; nt < NTILES; nt += 2) {
                uint32_t bo = SWZ128((uint32_t)((browb + nt * 8) * 128 + bkb));
                uint32_t bh4[4], bl4[4];
                ldsm4(bh4, sb + B_HI + bo);
                ldsm4(bl4, sb + B_LO + bo);
                mma16816(acc[0][nt], ah[0], bh4);
                mma16816(acc[0][nt], ah[0], bl4);
                mma16816(acc[0][nt], al[0], bh4);
                mma16816(acc[1][nt], ah[1], bh4);
                mma16816(acc[1][nt], ah[1], bl4);
                mma16816(acc[1][nt], al[1], bh4);
                mma16816(acc[0][nt + 1], ah[0], bh4 + 2);
                mma16816(acc[0][nt + 1], ah[0], bl4 + 2);
                mma16816(acc[0][nt + 1], al[0], bh4 + 2);
                mma16816(acc[1][nt + 1], ah[1], bh4 + 2);
                mma16816(acc[1][nt + 1], ah[1], bl4 + 2);
                mma16816(acc[1][nt + 1], al[1], bh4 + 2);
            }
        }
        __syncthreads();
    }

    // ---------------- stage D in SMEM (reuse buffers), row-wise epilogue ----------
    float* Dsm = (float*)base;   // [128][NT]
#pragma unroll
    for (int mb = 0; mb < 2; mb++) {
        const int r0 = wm * 32 + mb * 16 + (lane >> 2);
        const int c0 = wn * NW + (lane & 3) * 2;
#pragma unroll
        for (int nt = 0; nt < NTILES; nt++) {
            *(float2*)&Dsm[r0 * NT + c0 + nt * 8] = make_float2(acc[mb][nt][0], acc[mb][nt][1]);
            *(float2*)&Dsm[(r0 + 8) * NT + c0 + nt * 8] = make_float2(acc[mb][nt][2], acc[mb][nt][3]);
        }
    }
    __syncthreads();

    constexpr int NJ = NT / 32;
    for (int rr = 0; rr < 16; rr++) {
        const int r = wid * 16 + rr;
        const int gr = bm0 + r;
        const bool rv = gr < N_NODES;
        float v[NJ];
#pragma unroll
        for (int j = 0; j < NJ; j++) {
            int c = lane + 32 * j;
            v[j] = Dsm[r * NT + c] + bias[(EPI == 0 ? n0 : 0) + c];
        }

        if (EPI == 0) {
            if (rv) {
#pragma unroll
                for (int j = 0; j < NJ; j++)
                    g_AB[(size_t)gr * 320 + n0 + lane + 32 * j] = __float2half(v[j]);
                if (n0 == 0) {
#pragma unroll
                    for (int j = 0; j < NJ; j++)
                        g_msum[(size_t)gr * 160 + lane + 32 * j] = 0.f;
                }
            }
        } else if (EPI == 1 || EPI == 2) {
            float s = 0.f, q = 0.f;
#pragma unroll
            for (int j = 0; j < NJ; j++) { s += v[j]; q += v[j] * v[j]; }
            float mean = wsum(s) * (1.f / NT);
            float var = wsum(q) * (1.f / NT) - mean * mean;
            float rstd = rsqrtf(var + LN_EPS);
            if (rv) {
                if (EPI == 1) {
#pragma unroll
                    for (int j = 0; j < NJ; j++) {
                        int c = lane + 32 * j;
                        float hv = fmaxf(0.f, (v[j] - mean) * rstd * a0[c] + a1[c]);
                        Y[(size_t)gr * ldy + c] = hv;
                        st_split1(g_hh, g_hl, (size_t)gr * 192 + c, hv);
                    }
                    float t0 = a2[gr];
                    float tv = t0 * a3[lane] + a4[lane];
                    float tm = wsum(tv) * (1.f / 32.f);
                    float td = tv - tm;
                    float tvar = wsum(td * td) * (1.f / 32.f);
                    float tr = rsqrtf(tvar + LN_EPS);
                    float to = fmaxf(0.f, td * tr * a5[lane] + a6[lane]);
                    Y[(size_t)gr * ldy + 128 + lane] = to;
                    st_split1(g_hh, g_hl, (size_t)gr * 192 + 128 + lane, to);
                    g_hh[(size_t)gr * 192 + 160 + lane] = __float2bfloat16(0.f);
                    g_hl[(size_t)gr * 192 + 160 + lane] = __float2bfloat16(0.f);
                } else {
                    float tw = a2[gr];
#pragma unroll
                    for (int j = 0; j < NJ; j++) {
                        int c = lane + 32 * j;
                        float hn = fmaxf(0.f, (v[j] - mean) * rstd * a0[c] + a1[c]);
                        float ho = w0[(size_t)gr * 160 + c];
                        float hv = tw * hn + (1.f - tw) * ho;
                        w0[(size_t)gr * 160 + c] = hv;
                        st_split1(g_hh, g_hl, (size_t)gr * 192 + c, hv);
                    }
                    g_hh[(size_t)gr * 192 + 160 + lane] = __float2bfloat16(0.f);
                    g_hl[(size_t)gr * 192 + 160 + lane] = __float2bfloat16(0.f);
                }
            }
        } else {  // EPI == 3
            float q = 0.f;
#pragma unroll
            for (int j = 0; j < NJ; j++) q += v[j] * v[j];
            float sc = 1.f / fmaxf(sqrtf(wsum(q)), 1e-12f);
            if (rv) {
#pragma unroll
                for (int j = 0; j < NJ; j++)
                    Y[(size_t)gr * ldy + lane + 32 * j] = v[j] * sc;
            }
        }
    }
}

// ================= weight / input split kernels =================
__global__ void split_w(const float* __restrict__ W, __nv_bfloat16* __restrict__ H,
                        __nv_bfloat16* __restrict__ L, int NR, int K, int KPAD) {
    int t = blockIdx.x * blockDim.x + threadIdx.x;
    if (t >= NR * KPAD) return;
    int r = t / KPAD, c = t - r * KPAD;
    float v = (c < K) ? W[r * K + c] : 0.f;
    __nv_bfloat16 h = __float2bfloat16(v);
    H[t] = h;
    L[t] = __float2bfloat16(v - __bfloat162float(h));
}
__global__ void split_msg(const float* __restrict__ wm, const float* __restrict__ bm) {
    int t = blockIdx.x * blockDim.x + threadIdx.x;
    if (t < 320 * 192) {
        int r = t / 192, c = t - r * 192;
        float v = 0.f;
        if (c < 160) v = (r < 160) ? wm[r * 320 + c] : wm[(r - 160) * 320 + 160 + c];
        __nv_bfloat16 h = __float2bfloat16(v);
        g_wmh[t] = h;
        g_wml[t] = __float2bfloat16(v - __bfloat162float(h));
    }
    if (t < 320) g_bias320[t] = (t < 160) ? bm[t] : 0.f;
}

// ================= degree =================
__global__ void zero_cnt() {
    int i = blockIdx.x * blockDim.x + threadIdx.x;
    if (i < N_NODES) g_cnt[i] = 0.f;
}
__global__ void degree_kernel(const int* __restrict__ ei) {
    int e = blockIdx.x * blockDim.x + threadIdx.x;
    if (e < N_EDGES) atomicAdd(&g_cnt[ei[N_EDGES + e]], 1.0f);
}

// ================= edge pass (fp16 gather, fp32 atomic scatter) =================
__global__ void edge_kernel(const int* __restrict__ ei, const float* __restrict__ ew,
                            const float* __restrict__ gmv, const float* __restrict__ bemv)
{
    int w = (blockIdx.x * blockDim.x + threadIdx.x) >> 5;
    int lane = threadIdx.x & 31;
    if (w >= N_EDGES) return;
    int src = ei[w];
    int dst = ei[N_EDGES + w];
    float ewt = ew[w];
    const bool act = lane < 20;

    float v[8];
#pragma unroll
    for (int k = 0; k < 8; k++) v[k] = 0.f;
    if (act) {
        uint4 sv = *(const uint4*)(g_AB + (size_t)src * 320 + lane * 8);
        uint4 dv = *(const uint4*)(g_AB + (size_t)dst * 320 + 160 + lane * 8);
        const __half2* sh = (const __half2*)&sv;
        const __half2* dh = (const __half2*)&dv;
#pragma unroll
        for (int k = 0; k < 4; k++) {
            float2 a = __half22float2(sh[k]);
            float2 b = __half22float2(dh[k]);
            v[2 * k + 0] = a.x + b.x;
            v[2 * k + 1] = a.y + b.y;
        }
    }

    float s = 0.f;
#pragma unroll
    for (int k = 0; k < 8; k++) s += v[k];
    float mean = wsum(s) * (1.0f / 160.0f);

    float q = 0.f;
    if (act) {
#pragma unroll
        for (int k = 0; k < 8; k++) q += (v[k] - mean) * (v[k] - mean);
    }
    float var = wsum(q) * (1.0f / 160.0f);
    float rstd = rsqrtf(var + LN_EPS);

    if (act) {
        const int c0 = lane * 8;
        float4 g0 = ((const float4*)gmv)[2 * lane];
        float4 g1 = ((const float4*)gmv)[2 * lane + 1];
        float4 b0 = ((const float4*)bemv)[2 * lane];
        float4 b1 = ((const float4*)bemv)[2 * lane + 1];
        float* basep = g_msum + (size_t)dst * 160 + c0;
        float4 o0, o1;
        o0.x = fmaxf(0.f, (v[0] - mean) * rstd * g0.x + b0.x) * ewt;
        o0.y = fmaxf(0.f, (v[1] - mean) * rstd * g0.y + b0.y) * ewt;
        o0.z = fmaxf(0.f, (v[2] - mean) * rstd * g0.z + b0.z) * ewt;
        o0.w = fmaxf(0.f, (v[3] - mean) * rstd * g0.w + b0.w) * ewt;
        o1.x = fmaxf(0.f, (v[4] - mean) * rstd * g1.x + b1.x) * ewt;
        o1.y = fmaxf(0.f, (v[5] - mean) * rstd * g1.y + b1.y) * ewt;
        o1.z = fmaxf(0.f, (v[6] - mean) * rstd * g1.z + b1.z) * ewt;
        o1.w = fmaxf(0.f, (v[7] - mean) * rstd * g1.w + b1.w) * ewt;
        red4(basep, o0);
        red4(basep + 4, o1);
    }
}

// ================= node pass 1: message split to bf16 + gate tw =================
__global__ void node1_kernel(const float* __restrict__ wgv, const float* __restrict__ bgv) {
    int n = (blockIdx.x * blockDim.x + threadIdx.x) >> 5;
    int lane = threadIdx.x & 31;
    if (n >= N_NODES) return;
    const bool act = lane < 20;

    float c = g_cnt[n];
    float inv = (c > 0.f) ? 1.f / (c + 1e-8f) : 0.f;

    float dotp = 0.f;
    if (act) {
        const int c0 = lane * 8;
        float4 m0 = *(const float4*)(g_msum + (size_t)n * 160 + c0);
        float4 m1 = *(const float4*)(g_msum + (size_t)n * 160 + c0 + 4);
        m0.x *= inv; m0.y *= inv; m0.z *= inv; m0.w *= inv;
        m1.x *= inv; m1.y *= inv; m1.z *= inv; m1.w *= inv;
        st_split4(g_mh, g_ml, (size_t)n * 160 + c0, m0);
        st_split4(g_mh, g_ml, (size_t)n * 160 + c0 + 4, m1);
        float4 h0 = *(const float4*)(g_h + (size_t)n * 160 + c0);
        float4 h1 = *(const float4*)(g_h + (size_t)n * 160 + c0 + 4);
        float4 w0v = ((const float4*)wgv)[2 * lane];
        float4 w1v = ((const float4*)wgv)[2 * lane + 1];
        dotp = h0.x * w0v.x + h0.y * w0v.y + h0.z * w0v.z + h0.w * w0v.w
             + h1.x * w1v.x + h1.y * w1v.y + h1.z * w1v.z + h1.w * w1v.w;
    }
    float tot = wsum(dotp);
    if (lane == 0) g_tw[n] = 1.f / (1.f + expf(-(tot + bgv[0])));
}

// ================= host orchestration =================
extern "C" void kernel_launch(void* const* d_in, const int* in_sizes, int n_in,
                              void* d_out, int out_size)
{
    const float* node_features = (const float*)d_in[0];
    const int*   edge_index    = (const int*)d_in[1];
    const float* edge_weights  = (const float*)d_in[2];
    const float* time_steps    = (const float*)d_in[3];
    const float* w_enc   = (const float*)d_in[4];
    const float* b_enc   = (const float*)d_in[5];
    const float* g_enc   = (const float*)d_in[6];
    const float* be_enc  = (const float*)d_in[7];
    const float* w_time  = (const float*)d_in[8];
    const float* b_time  = (const float*)d_in[9];
    const float* g_time  = (const float*)d_in[10];
    const float* be_time = (const float*)d_in[11];
    const float* wm  = (const float*)d_in[12];
    const float* bm  = (const float*)d_in[13];
    const float* gm  = (const float*)d_in[14];
    const float* bem = (const float*)d_in[15];
    const float* wu  = (const float*)d_in[16];
    const float* bu  = (const float*)d_in[17];
    const float* gu  = (const float*)d_in[18];
    const float* beu = (const float*)d_in[19];
    const float* wg  = (const float*)d_in[20];
    const float* bg  = (const float*)d_in[21];
    const float* w_out = (const float*)d_in[22];
    const float* b_out = (const float*)d_in[23];
    float* out = (float*)d_out;

    float *p_h, *p_tw, *p_b320;
    __nv_bfloat16 *p_ah, *p_al, *p_hh, *p_hl, *p_mh, *p_ml;
    __nv_bfloat16 *p_weh, *p_wel, *p_wmh, *p_wml, *p_wuh, *p_wul, *p_woh, *p_wol;
    cudaGetSymbolAddress((void**)&p_h, g_h);
    cudaGetSymbolAddress((void**)&p_tw, g_tw);
    cudaGetSymbolAddress((void**)&p_b320, g_bias320);
    cudaGetSymbolAddress((void**)&p_ah, g_ah);
    cudaGetSymbolAddress((void**)&p_al, g_al);
    cudaGetSymbolAddress((void**)&p_hh, g_hh);
    cudaGetSymbolAddress((void**)&p_hl, g_hl);
    cudaGetSymbolAddress((void**)&p_mh, g_mh);
    cudaGetSymbolAddress((void**)&p_ml, g_ml);
    cudaGetSymbolAddress((void**)&p_weh, g_weh);
    cudaGetSymbolAddress((void**)&p_wel, g_wel);
    cudaGetSymbolAddress((void**)&p_wmh, g_wmh);
    cudaGetSymbolAddress((void**)&p_wml, g_wml);
    cudaGetSymbolAddress((void**)&p_wuh, g_wuh);
    cudaGetSymbolAddress((void**)&p_wul, g_wul);
    cudaGetSymbolAddress((void**)&p_woh, g_woh);
    cudaGetSymbolAddress((void**)&p_wol, g_wol);

    const int GBM = (N_NODES + 127) / 128;                   // 782
    const int NODE_WARP_BLOCKS = (N_NODES * 32 + 255) / 256; // 12500
    const int EDGE_WARP_BLOCKS = (N_EDGES * 32 + 255) / 256; // 100000

    const int SM160 = 128 * 160 * 4 + 1024;   // 82944
    const int SM128 = 128 * 128 * 4 + 1024;   // 66560
    cudaFuncSetAttribute(gemm_tc<128, 128, 1, false>, cudaFuncAttributeMaxDynamicSharedMemorySize, SM128);
    cudaFuncSetAttribute(gemm_tc<160, 192, 0, false>, cudaFuncAttributeMaxDynamicSharedMemorySize, SM160);
    cudaFuncSetAttribute(gemm_tc<160, 320, 2, true>,  cudaFuncAttributeMaxDynamicSharedMemorySize, SM160);
    cudaFuncSetAttribute(gemm_tc<128, 192, 3, false>, cudaFuncAttributeMaxDynamicSharedMemorySize, SM128);

    // degrees (constant across layers)
    zero_cnt<<<(N_NODES + 255) / 256, 256>>>();
    degree_kernel<<<(N_EDGES + 255) / 256, 256>>>(edge_index);

    // split inputs/weights for encoder
    split_w<<<(N_NODES * 128 + 255) / 256, 256>>>(node_features, p_ah, p_al, N_NODES, 128, 128);
    split_w<<<(128 * 128 + 255) / 256, 256>>>(w_enc, p_weh, p_wel, 128, 128, 128);
    gemm_tc<128, 128, 1, false><<<dim3(1, GBM), 256, SM128>>>(
        p_ah, p_al, nullptr, nullptr, p_weh, p_wel, b_enc, p_h, 160,
        g_enc, be_enc, time_steps, w_time, b_time, g_time, be_time, nullptr);

    for (int l = 0; l < 2; l++) {
        split_msg<<<(320 * 192 + 255) / 256, 256>>>(wm + (size_t)l * 160 * 320, bm + l * 160);
        // message GEMM (+ fused zero of g_msum by n0==0 CTAs)
        gemm_tc<160, 192, 0, false><<<dim3(2, GBM), 256, SM160>>>(
            p_hh, p_hl, nullptr, nullptr, p_wmh, p_wml, p_b320, nullptr, 0,
            nullptr, nullptr, nullptr, nullptr, nullptr, nullptr, nullptr, nullptr);
        edge_kernel<<<EDGE_WARP_BLOCKS, 256>>>(edge_index, edge_weights, gm + l * 160, bem + l * 160);
        node1_kernel<<<NODE_WARP_BLOCKS, 256>>>(wg + l * 160, bg + l);
        split_w<<<(160 * 320 + 255) / 256, 256>>>(wu + (size_t)l * 160 * 320, p_wuh, p_wul, 160, 320, 320);
        // update GEMM: A = [h split | message split] dual-source
        gemm_tc<160, 320, 2, true><<<dim3(1, GBM), 256, SM160>>>(
            p_hh, p_hl, p_mh, p_ml, p_wuh, p_wul, bu + l * 160, nullptr, 0,
            gu + l * 160, beu + l * 160, p_tw, nullptr, nullptr, nullptr, nullptr, p_h);
    }

    split_w<<<(128 * 192 + 255) / 256, 256>>>(w_out, p_woh, p_wol, 128, 160, 192);
    gemm_tc<128, 192, 3, false><<<dim3(1, GBM), 256, SM128>>>(
        p_hh, p_hl, nullptr, nullptr, p_woh, p_wol, b_out, out, 128,
        nullptr, nullptr, nullptr, nullptr, nullptr, nullptr, nullptr, nullptr);
}

// round 13
// speedup vs baseline: 1.4958x; 1.4958x over previous
#include <cuda_runtime.h>
#include <cuda_bf16.h>
#include <cuda_fp16.h>
#include <math.h>
#include <stdint.h>

#define N_NODES 100000
#define NROWS_PAD 100096          // 782 * 128
#define N_EDGES 800000
#define LN_EPS 1e-5f

// ================= scratch (device globals; no allocation allowed) =================
__device__ float g_h[(size_t)N_NODES * 160];      // node state fp32
__device__ __half g_AB[(size_t)NROWS_PAD * 320];  // message A|B fp16 (L2-resident)
__device__ __half g_msum[(size_t)N_NODES * 160];  // scatter-add accumulator (fp16)
__device__ float g_cnt[N_NODES];                  // in-degree
__device__ float g_tw[N_NODES];                   // gate
__device__ float g_bias320[320];                  // [bm | 0]

// bf16 hi/lo pre-split GEMM A operands
__device__ __align__(16) __nv_bfloat16 g_ah[(size_t)NROWS_PAD * 128], g_al[(size_t)NROWS_PAD * 128];   // node_features
__device__ __align__(16) __nv_bfloat16 g_hh[(size_t)NROWS_PAD * 192], g_hl[(size_t)NROWS_PAD * 192];   // h (K=160 pad 192)
__device__ __align__(16) __nv_bfloat16 g_uh[(size_t)NROWS_PAD * 320], g_ul[(size_t)NROWS_PAD * 320];   // U=[h|msg]

// bf16 hi/lo split weights (zero-padded K)
__device__ __align__(16) __nv_bfloat16 g_weh[128 * 128], g_wel[128 * 128];   // encoder
__device__ __align__(16) __nv_bfloat16 g_wmh[320 * 192], g_wml[320 * 192];   // message
__device__ __align__(16) __nv_bfloat16 g_wuh[160 * 320], g_wul[160 * 320];   // update
__device__ __align__(16) __nv_bfloat16 g_woh[128 * 192], g_wol[128 * 192];   // output

// ================= helpers =================
__device__ __forceinline__ uint32_t smem_u32(const void* p) {
    uint32_t a;
    asm("{ .reg .u64 t; cvta.to.shared.u64 t, %1; cvt.u32.u64 %0, t; }" : "=r"(a) : "l"(p));
    return a;
}
#define SWZ128(o) ((o) ^ (((o) >> 3) & 0x70))

__device__ __forceinline__ void cpa16(uint32_t dst, const void* src) {
    asm volatile("cp.async.cg.shared.global [%0], [%1], 16;" :: "r"(dst), "l"(src));
}
#define CP_COMMIT() asm volatile("cp.async.commit_group;" ::: "memory")
#define CP_WAIT0()  asm volatile("cp.async.wait_group 0;" ::: "memory")

__device__ __forceinline__ void ldsm4(uint32_t* r, uint32_t addr) {
    asm volatile("ldmatrix.sync.aligned.m8n8.x4.shared.b16 {%0,%1,%2,%3}, [%4];"
        : "=r"(r[0]), "=r"(r[1]), "=r"(r[2]), "=r"(r[3]) : "r"(addr));
}
__device__ __forceinline__ void mma16816(float* d, const uint32_t* a, const uint32_t* b) {
    asm volatile("mma.sync.aligned.m16n8k16.row.col.f32.bf16.bf16.f32 "
        "{%0,%1,%2,%3},{%4,%5,%6,%7},{%8,%9},{%0,%1,%2,%3};"
        : "+f"(d[0]), "+f"(d[1]), "+f"(d[2]), "+f"(d[3])
        : "r"(a[0]), "r"(a[1]), "r"(a[2]), "r"(a[3]), "r"(b[0]), "r"(b[1]));
}
__device__ __forceinline__ void split2(float a, float b, uint32_t& hi, uint32_t& lo) {
    __nv_bfloat16 ha = __float2bfloat16(a), hb = __float2bfloat16(b);
    __nv_bfloat16 la = __float2bfloat16(a - __bfloat162float(ha));
    __nv_bfloat16 lb = __float2bfloat16(b - __bfloat162float(hb));
    hi = (uint32_t)__bfloat16_as_ushort(ha) | ((uint32_t)__bfloat16_as_ushort(hb) << 16);
    lo = (uint32_t)__bfloat16_as_ushort(la) | ((uint32_t)__bfloat16_as_ushort(lb) << 16);
}
__device__ __forceinline__ void st_split1(__nv_bfloat16* H, __nv_bfloat16* L, size_t idx, float v) {
    __nv_bfloat16 h = __float2bfloat16(v);
    H[idx] = h;
    L[idx] = __float2bfloat16(v - __bfloat162float(h));
}
__device__ __forceinline__ void st_split4(__nv_bfloat16* H, __nv_bfloat16* L, size_t idx, float4 v) {
    uint2 hp, lp;
    split2(v.x, v.y, hp.x, lp.x);
    split2(v.z, v.w, hp.y, lp.y);
    *(uint2*)(H + idx) = hp;
    *(uint2*)(L + idx) = lp;
}
__device__ __forceinline__ float wsum(float v) {
#pragma unroll
    for (int o = 16; o; o >>= 1) v += __shfl_xor_sync(0xffffffffu, v, o);
    return v;
}
// fp16x2 vector reduction: 8 half channels per op
__device__ __forceinline__ void red8h(__half* p, float4 a, float4 b) {
    __half2 h0 = __floats2half2_rn(a.x, a.y);
    __half2 h1 = __floats2half2_rn(a.z, a.w);
    __half2 h2 = __floats2half2_rn(b.x, b.y);
    __half2 h3 = __floats2half2_rn(b.z, b.w);
    asm volatile("red.global.add.noftz.v4.f16x2 [%0], {%1,%2,%3,%4};"
                 :: "l"(p),
                    "r"(*(uint32_t*)&h0), "r"(*(uint32_t*)&h1),
                    "r"(*(uint32_t*)&h2), "r"(*(uint32_t*)&h3) : "memory");
}

// ================= tensor-core GEMM (mma.sync bf16x3 split), fused epilogues ======
// D[128, NT] tile = X[128, KPAD] @ W[NT, KPAD]^T (pre-split bf16 hi/lo operands).  EPI:
//   0: bias + store fp16 to g_AB (+n0 col offset, stride 320)         (message precompute)
//   1: bias + LN(NT)+relu -> Y cols 0..127 (ldy) + g_hh/g_hl split; time enc col 128+lane
//   2: bias + LN(NT)+relu + gate blend into w0 + g_hh/g_hl split (node update)
//   3: bias + row L2-normalize -> Y (output projection)
template<int NT, int KPAD, int EPI>
__global__ __launch_bounds__(256, 2) void gemm_tc(
    const __nv_bfloat16* __restrict__ Xh, const __nv_bfloat16* __restrict__ Xl,
    const __nv_bfloat16* __restrict__ Wh, const __nv_bfloat16* __restrict__ Wl,
    const float* __restrict__ bias,
    float* __restrict__ Y, int ldy,
    const float* __restrict__ a0, const float* __restrict__ a1,
    const float* __restrict__ a2, const float* __restrict__ a3,
    const float* __restrict__ a4, const float* __restrict__ a5,
    const float* __restrict__ a6,
    float* __restrict__ w0)
{
    extern __shared__ __align__(16) char dsm[];
    char* base = (char*)((((uintptr_t)dsm) + 1023) & ~(uintptr_t)1023);
    const uint32_t sb = smem_u32(base);
    constexpr int A_HI = 0, A_LO = 16384, B_HI = 32768;
    constexpr int B_LO = 32768 + NT * 128;
    constexpr int NW = NT / 2;
    constexpr int NTILES = NW / 8;
    const int tid = threadIdx.x, wid = tid >> 5, lane = tid & 31;
    const int wm = wid & 3, wn = wid >> 2;
    const int bm0 = blockIdx.y * 128, n0 = blockIdx.x * NT;

    float acc[2][NTILES][4];
#pragma unroll
    for (int m = 0; m < 2; m++)
#pragma unroll
        for (int t = 0; t < NTILES; t++)
#pragma unroll
            for (int j = 0; j < 4; j++) acc[m][t][j] = 0.f;

    constexpr int NCHUNK = KPAD / 64;
    for (int ch = 0; ch < NCHUNK; ch++) {
        const int c0 = ch * 64;
#pragma unroll
        for (int s = tid; s < 128 * 8; s += 256) {
            int r = s >> 3, i = s & 7;
            uint32_t off = SWZ128((uint32_t)(r * 128 + i * 16));
            cpa16(sb + A_HI + off, Xh + (size_t)(bm0 + r) * KPAD + c0 + i * 8);
            cpa16(sb + A_LO + off, Xl + (size_t)(bm0 + r) * KPAD + c0 + i * 8);
        }
        for (int s = tid; s < NT * 8; s += 256) {
            int r = s >> 3, i = s & 7;
            uint32_t off = SWZ128((uint32_t)(r * 128 + i * 16));
            cpa16(sb + B_HI + off, Wh + (size_t)(n0 + r) * KPAD + c0 + i * 8);
            cpa16(sb + B_LO + off, Wl + (size_t)(n0 + r) * KPAD + c0 + i * 8);
        }
        CP_COMMIT();
        CP_WAIT0();
        __syncthreads();

#pragma unroll
        for (int ks = 0; ks < 4; ks++) {
            uint32_t ah[2][4], al[2][4];
            const int arow = wm * 32 + (lane & 15);
            const int akb = ks * 32 + ((lane >> 4) << 4);
            {
                uint32_t o0 = SWZ128((uint32_t)(arow * 128 + akb));
                ldsm4(ah[0], sb + A_HI + o0);
                ldsm4(al[0], sb + A_LO + o0);
                uint32_t o1 = SWZ128((uint32_t)((arow + 16) * 128 + akb));
                ldsm4(ah[1], sb + A_HI + o1);
                ldsm4(al[1], sb + A_LO + o1);
            }
            const int q = lane >> 3;
            const int browb = wn * NW + ((q >> 1) << 3) + (lane & 7);
            const int bkb = ks * 32 + (q & 1) * 16;
#pragma unroll
            for (int nt = 0; nt < NTILES; nt += 2) {
                uint32_t bo = SWZ128((uint32_t)((browb + nt * 8) * 128 + bkb));
                uint32_t bh4[4], bl4[4];
                ldsm4(bh4, sb + B_HI + bo);
                ldsm4(bl4, sb + B_LO + bo);
                mma16816(acc[0][nt], ah[0], bh4);
                mma16816(acc[0][nt], ah[0], bl4);
                mma16816(acc[0][nt], al[0], bh4);
                mma16816(acc[1][nt], ah[1], bh4);
                mma16816(acc[1][nt], ah[1], bl4);
                mma16816(acc[1][nt], al[1], bh4);
                mma16816(acc[0][nt + 1], ah[0], bh4 + 2);
                mma16816(acc[0][nt + 1], ah[0], bl4 + 2);
                mma16816(acc[0][nt + 1], al[0], bh4 + 2);
                mma16816(acc[1][nt + 1], ah[1], bh4 + 2);
                mma16816(acc[1][nt + 1], ah[1], bl4 + 2);
                mma16816(acc[1][nt + 1], al[1], bh4 + 2);
            }
        }
        __syncthreads();
    }

    // ---------------- stage D in SMEM (reuse buffers), row-wise epilogue ----------
    float* Dsm = (float*)base;   // [128][NT]
#pragma unroll
    for (int mb = 0; mb < 2; mb++) {
        const int r0 = wm * 32 + mb * 16 + (lane >> 2);
        const int c0 = wn * NW + (lane & 3) * 2;
#pragma unroll
        for (int nt = 0; nt < NTILES; nt++) {
            *(float2*)&Dsm[r0 * NT + c0 + nt * 8] = make_float2(acc[mb][nt][0], acc[mb][nt][1]);
            *(float2*)&Dsm[(r0 + 8) * NT + c0 + nt * 8] = make_float2(acc[mb][nt][2], acc[mb][nt][3]);
        }
    }
    __syncthreads();

    constexpr int NJ = NT / 32;
    for (int rr = 0; rr < 16; rr++) {
        const int r = wid * 16 + rr;
        const int gr = bm0 + r;
        const bool rv = gr < N_NODES;
        float v[NJ];
#pragma unroll
        for (int j = 0; j < NJ; j++) {
            int c = lane + 32 * j;
            v[j] = Dsm[r * NT + c] + bias[(EPI == 0 ? n0 : 0) + c];
        }

        if (EPI == 0) {
            if (rv) {
#pragma unroll
                for (int j = 0; j < NJ; j++)
                    g_AB[(size_t)gr * 320 + n0 + lane + 32 * j] = __float2half(v[j]);
            }
        } else if (EPI == 1 || EPI == 2) {
            float s = 0.f, q = 0.f;
#pragma unroll
            for (int j = 0; j < NJ; j++) { s += v[j]; q += v[j] * v[j]; }
            float mean = wsum(s) * (1.f / NT);
            float var = wsum(q) * (1.f / NT) - mean * mean;
            float rstd = rsqrtf(var + LN_EPS);
            if (rv) {
                if (EPI == 1) {
#pragma unroll
                    for (int j = 0; j < NJ; j++) {
                        int c = lane + 32 * j;
                        float hv = fmaxf(0.f, (v[j] - mean) * rstd * a0[c] + a1[c]);
                        Y[(size_t)gr * ldy + c] = hv;
                        st_split1(g_hh, g_hl, (size_t)gr * 192 + c, hv);
                    }
                    float t0 = a2[gr];
                    float tv = t0 * a3[lane] + a4[lane];
                    float tm = wsum(tv) * (1.f / 32.f);
                    float td = tv - tm;
                    float tvar = wsum(td * td) * (1.f / 32.f);
                    float tr = rsqrtf(tvar + LN_EPS);
                    float to = fmaxf(0.f, td * tr * a5[lane] + a6[lane]);
                    Y[(size_t)gr * ldy + 128 + lane] = to;
                    st_split1(g_hh, g_hl, (size_t)gr * 192 + 128 + lane, to);
                    g_hh[(size_t)gr * 192 + 160 + lane] = __float2bfloat16(0.f);
                    g_hl[(size_t)gr * 192 + 160 + lane] = __float2bfloat16(0.f);
                } else {
                    float tw = a2[gr];
#pragma unroll
                    for (int j = 0; j < NJ; j++) {
                        int c = lane + 32 * j;
                        float hn = fmaxf(0.f, (v[j] - mean) * rstd * a0[c] + a1[c]);
                        float ho = w0[(size_t)gr * 160 + c];
                        float hv = tw * hn + (1.f - tw) * ho;
                        w0[(size_t)gr * 160 + c] = hv;
                        st_split1(g_hh, g_hl, (size_t)gr * 192 + c, hv);
                    }
                    g_hh[(size_t)gr * 192 + 160 + lane] = __float2bfloat16(0.f);
                    g_hl[(size_t)gr * 192 + 160 + lane] = __float2bfloat16(0.f);
                }
            }
        } else {  // EPI == 3
            float q = 0.f;
#pragma unroll
            for (int j = 0; j < NJ; j++) q += v[j] * v[j];
            float sc = 1.f / fmaxf(sqrtf(wsum(q)), 1e-12f);
            if (rv) {
#pragma unroll
                for (int j = 0; j < NJ; j++)
                    Y[(size_t)gr * ldy + lane + 32 * j] = v[j] * sc;
            }
        }
    }
}

// ================= weight / input split kernels =================
__global__ void split_w(const float* __restrict__ W, __nv_bfloat16* __restrict__ H,
                        __nv_bfloat16* __restrict__ L, int NR, int K, int KPAD) {
    int t = blockIdx.x * blockDim.x + threadIdx.x;
    if (t >= NR * KPAD) return;
    int r = t / KPAD, c = t - r * KPAD;
    float v = (c < K) ? W[r * K + c] : 0.f;
    __nv_bfloat16 h = __float2bfloat16(v);
    H[t] = h;
    L[t] = __float2bfloat16(v - __bfloat162float(h));
}
__global__ void split_msg(const float* __restrict__ wm, const float* __restrict__ bm) {
    int t = blockIdx.x * blockDim.x + threadIdx.x;
    if (t < 320 * 192) {
        int r = t / 192, c = t - r * 192;
        float v = 0.f;
        if (c < 160) v = (r < 160) ? wm[r * 320 + c] : wm[(r - 160) * 320 + 160 + c];
        __nv_bfloat16 h = __float2bfloat16(v);
        g_wmh[t] = h;
        g_wml[t] = __float2bfloat16(v - __bfloat162float(h));
    }
    if (t < 320) g_bias320[t] = (t < 160) ? bm[t] : 0.f;
}

// ================= zero / degree =================
__global__ void zero_cnt() {
    int i = blockIdx.x * blockDim.x + threadIdx.x;
    if (i < N_NODES) g_cnt[i] = 0.f;
}
__global__ void zero_msum() {
    int i = blockIdx.x * blockDim.x + threadIdx.x;
    int st = gridDim.x * blockDim.x;
    uint4* p = (uint4*)g_msum;
    const int n4 = N_NODES * 20;   // 160 halves = 20 uint4 per node
    uint4 z = make_uint4(0, 0, 0, 0);
    for (int k = i; k < n4; k += st) p[k] = z;
}
__global__ void degree_kernel(const int* __restrict__ ei) {
    int e = blockIdx.x * blockDim.x + threadIdx.x;
    if (e < N_EDGES) atomicAdd(&g_cnt[ei[N_EDGES + e]], 1.0f);
}

// ================= edge pass (fp16 gather, fp16x2 vector-reduction scatter) ========
__global__ void edge_kernel(const int* __restrict__ ei, const float* __restrict__ ew,
                            const float* __restrict__ gmv, const float* __restrict__ bemv)
{
    int w = (blockIdx.x * blockDim.x + threadIdx.x) >> 5;
    int lane = threadIdx.x & 31;
    if (w >= N_EDGES) return;
    int src = ei[w];
    int dst = ei[N_EDGES + w];
    float ewt = ew[w];
    const bool act = lane < 20;

    float v[8];
#pragma unroll
    for (int k = 0; k < 8; k++) v[k] = 0.f;
    if (act) {
        uint4 sv = *(const uint4*)(g_AB + (size_t)src * 320 + lane * 8);
        uint4 dv = *(const uint4*)(g_AB + (size_t)dst * 320 + 160 + lane * 8);
        const __half2* sh = (const __half2*)&sv;
        const __half2* dh = (const __half2*)&dv;
#pragma unroll
        for (int k = 0; k < 4; k++) {
            float2 a = __half22float2(sh[k]);
            float2 b = __half22float2(dh[k]);
            v[2 * k + 0] = a.x + b.x;
            v[2 * k + 1] = a.y + b.y;
        }
    }

    float s = 0.f;
#pragma unroll
    for (int k = 0; k < 8; k++) s += v[k];
    float mean = wsum(s) * (1.0f / 160.0f);

    float q = 0.f;
    if (act) {
#pragma unroll
        for (int k = 0; k < 8; k++) q += (v[k] - mean) * (v[k] - mean);
    }
    float var = wsum(q) * (1.0f / 160.0f);
    float rstd = rsqrtf(var + LN_EPS);

    if (act) {
        const int c0 = lane * 8;
        float4 g0 = ((const float4*)gmv)[2 * lane];
        float4 g1 = ((const float4*)gmv)[2 * lane + 1];
        float4 b0 = ((const float4*)bemv)[2 * lane];
        float4 b1 = ((const float4*)bemv)[2 * lane + 1];
        float4 o0, o1;
        o0.x = fmaxf(0.f, (v[0] - mean) * rstd * g0.x + b0.x) * ewt;
        o0.y = fmaxf(0.f, (v[1] - mean) * rstd * g0.y + b0.y) * ewt;
        o0.z = fmaxf(0.f, (v[2] - mean) * rstd * g0.z + b0.z) * ewt;
        o0.w = fmaxf(0.f, (v[3] - mean) * rstd * g0.w + b0.w) * ewt;
        o1.x = fmaxf(0.f, (v[4] - mean) * rstd * g1.x + b1.x) * ewt;
        o1.y = fmaxf(0.f, (v[5] - mean) * rstd * g1.y + b1.y) * ewt;
        o1.z = fmaxf(0.f, (v[6] - mean) * rstd * g1.z + b1.z) * ewt;
        o1.w = fmaxf(0.f, (v[7] - mean) * rstd * g1.w + b1.w) * ewt;
        red8h(g_msum + (size_t)dst * 160 + c0, o0, o1);
    }
}

// ================= node pass 1: U=[h|messages] split to bf16, gate tw =============
__global__ void node1_kernel(const float* __restrict__ wgv, const float* __restrict__ bgv) {
    int n = (blockIdx.x * blockDim.x + threadIdx.x) >> 5;
    int lane = threadIdx.x & 31;
    if (n >= N_NODES) return;

    float c = g_cnt[n];
    float inv = (c > 0.f) ? 1.f / (c + 1e-8f) : 0.f;

    const float4* H = (const float4*)(g_h + (size_t)n * 160);
    const __half* Mbase = g_msum + (size_t)n * 160;
    const bool two = lane < 8;
    const size_t ub = (size_t)n * 320;

    float dotp = 0.f;
    {
        float4 h = H[lane];
        st_split4(g_uh, g_ul, ub + 4 * lane, h);
        uint2 mraw = *(const uint2*)(Mbase + 4 * lane);
        float2 f0 = __half22float2(*(const __half2*)&mraw.x);
        float2 f1 = __half22float2(*(const __half2*)&mraw.y);
        float4 mm = make_float4(f0.x * inv, f0.y * inv, f1.x * inv, f1.y * inv);
        st_split4(g_uh, g_ul, ub + 160 + 4 * lane, mm);
        float4 wg = ((const float4*)wgv)[lane];
        dotp = h.x * wg.x + h.y * wg.y + h.z * wg.z + h.w * wg.w;
    }
    if (two) {
        float4 h = H[lane + 32];
        st_split4(g_uh, g_ul, ub + 128 + 4 * lane, h);
        uint2 mraw = *(const uint2*)(Mbase + 128 + 4 * lane);
        float2 f0 = __half22float2(*(const __half2*)&mraw.x);
        float2 f1 = __half22float2(*(const __half2*)&mraw.y);
        float4 mm = make_float4(f0.x * inv, f0.y * inv, f1.x * inv, f1.y * inv);
        st_split4(g_uh, g_ul, ub + 160 + 128 + 4 * lane, mm);
        float4 wg = ((const float4*)wgv)[lane + 32];
        dotp += h.x * wg.x + h.y * wg.y + h.z * wg.z + h.w * wg.w;
    }
    float tot = wsum(dotp);
    if (lane == 0) g_tw[n] = 1.f / (1.f + expf(-(tot + bgv[0])));
}

// ================= host orchestration =================
extern "C" void kernel_launch(void* const* d_in, const int* in_sizes, int n_in,
                              void* d_out, int out_size)
{
    const float* node_features = (const float*)d_in[0];
    const int*   edge_index    = (const int*)d_in[1];
    const float* edge_weights  = (const float*)d_in[2];
    const float* time_steps    = (const float*)d_in[3];
    const float* w_enc   = (const float*)d_in[4];
    const float* b_enc   = (const float*)d_in[5];
    const float* g_enc   = (const float*)d_in[6];
    const float* be_enc  = (const float*)d_in[7];
    const float* w_time  = (const float*)d_in[8];
    const float* b_time  = (const float*)d_in[9];
    const float* g_time  = (const float*)d_in[10];
    const float* be_time = (const float*)d_in[11];
    const float* wm  = (const float*)d_in[12];
    const float* bm  = (const float*)d_in[13];
    const float* gm  = (const float*)d_in[14];
    const float* bem = (const float*)d_in[15];
    const float* wu  = (const float*)d_in[16];
    const float* bu  = (const float*)d_in[17];
    const float* gu  = (const float*)d_in[18];
    const float* beu = (const float*)d_in[19];
    const float* wg  = (const float*)d_in[20];
    const float* bg  = (const float*)d_in[21];
    const float* w_out = (const float*)d_in[22];
    const float* b_out = (const float*)d_in[23];
    float* out = (float*)d_out;

    float *p_h, *p_tw, *p_b320;
    __nv_bfloat16 *p_ah, *p_al, *p_hh, *p_hl, *p_uh, *p_ul;
    __nv_bfloat16 *p_weh, *p_wel, *p_wmh, *p_wml, *p_wuh, *p_wul, *p_woh, *p_wol;
    cudaGetSymbolAddress((void**)&p_h, g_h);
    cudaGetSymbolAddress((void**)&p_tw, g_tw);
    cudaGetSymbolAddress((void**)&p_b320, g_bias320);
    cudaGetSymbolAddress((void**)&p_ah, g_ah);
    cudaGetSymbolAddress((void**)&p_al, g_al);
    cudaGetSymbolAddress((void**)&p_hh, g_hh);
    cudaGetSymbolAddress((void**)&p_hl, g_hl);
    cudaGetSymbolAddress((void**)&p_uh, g_uh);
    cudaGetSymbolAddress((void**)&p_ul, g_ul);
    cudaGetSymbolAddress((void**)&p_weh, g_weh);
    cudaGetSymbolAddress((void**)&p_wel, g_wel);
    cudaGetSymbolAddress((void**)&p_wmh, g_wmh);
    cudaGetSymbolAddress((void**)&p_wml, g_wml);
    cudaGetSymbolAddress((void**)&p_wuh, g_wuh);
    cudaGetSymbolAddress((void**)&p_wul, g_wul);
    cudaGetSymbolAddress((void**)&p_woh, g_woh);
    cudaGetSymbolAddress((void**)&p_wol, g_wol);

    const int GBM = (N_NODES + 127) / 128;                   // 782
    const int NODE_WARP_BLOCKS = (N_NODES * 32 + 255) / 256; // 12500
    const int EDGE_WARP_BLOCKS = (N_EDGES * 32 + 255) / 256; // 100000

    const int SM160 = 128 * 160 * 4 + 1024;   // 82944
    const int SM128 = 128 * 128 * 4 + 1024;   // 66560
    cudaFuncSetAttribute(gemm_tc<128, 128, 1>, cudaFuncAttributeMaxDynamicSharedMemorySize, SM128);
    cudaFuncSetAttribute(gemm_tc<160, 192, 0>, cudaFuncAttributeMaxDynamicSharedMemorySize, SM160);
    cudaFuncSetAttribute(gemm_tc<160, 320, 2>, cudaFuncAttributeMaxDynamicSharedMemorySize, SM160);
    cudaFuncSetAttribute(gemm_tc<128, 192, 3>, cudaFuncAttributeMaxDynamicSharedMemorySize, SM128);

    // degrees (constant across layers)
    zero_cnt<<<(N_NODES + 255) / 256, 256>>>();
    degree_kernel<<<(N_EDGES + 255) / 256, 256>>>(edge_index);

    // split inputs/weights for encoder
    split_w<<<(N_NODES * 128 + 255) / 256, 256>>>(node_features, p_ah, p_al, N_NODES, 128, 128);
    split_w<<<(128 * 128 + 255) / 256, 256>>>(w_enc, p_weh, p_wel, 128, 128, 128);
    gemm_tc<128, 128, 1><<<dim3(1, GBM), 256, SM128>>>(
        p_ah, p_al, p_weh, p_wel, b_enc, p_h, 160,
        g_enc, be_enc, time_steps, w_time, b_time, g_time, be_time, nullptr);

    for (int l = 0; l < 2; l++) {
        split_msg<<<(320 * 192 + 255) / 256, 256>>>(wm + (size_t)l * 160 * 320, bm + l * 160);
        gemm_tc<160, 192, 0><<<dim3(2, GBM), 256, SM160>>>(
            p_hh, p_hl, p_wmh, p_wml, p_b320, nullptr, 0,
            nullptr, nullptr, nullptr, nullptr, nullptr, nullptr, nullptr, nullptr);
        zero_msum<<<4096, 256>>>();
        edge_kernel<<<EDGE_WARP_BLOCKS, 256>>>(edge_index, edge_weights, gm + l * 160, bem + l * 160);
        node1_kernel<<<NODE_WARP_BLOCKS, 256>>>(wg + l * 160, bg + l);
        split_w<<<(160 * 320 + 255) / 256, 256>>>(wu + (size_t)l * 160 * 320, p_wuh, p_wul, 160, 320, 320);
        gemm_tc<160, 320, 2><<<dim3(1, GBM), 256, SM160>>>(
            p_uh, p_ul, p_wuh, p_wul, bu + l * 160, nullptr, 0,
            gu + l * 160, beu + l * 160, p_tw, nullptr, nullptr, nullptr, nullptr, p_h);
    }

    split_w<<<(128 * 192 + 255) / 256, 256>>>(w_out, p_woh, p_wol, 128, 160, 192);
    gemm_tc<128, 192, 3><<<dim3(1, GBM), 256, SM128>>>(
        p_hh, p_hl, p_woh, p_wol, b_out, out, 128,
        nullptr, nullptr, nullptr, nullptr, nullptr, nullptr, nullptr, nullptr);
}

// round 14
// speedup vs baseline: 1.6033x; 1.0719x over previous
#include <cuda_runtime.h>
#include <cuda_bf16.h>
#include <cuda_fp16.h>
#include <math.h>
#include <stdint.h>

#define N_NODES 100000
#define NROWS_PAD 100096          // >= 1563 * 64
#define N_EDGES 800000
#define LN_EPS 1e-5f

// ================= scratch (device globals; no allocation allowed) =================
__device__ float g_h[(size_t)N_NODES * 160];      // node state fp32
__device__ __half g_AB[(size_t)NROWS_PAD * 320];  // message A|B fp16 (L2-resident)
__device__ __half g_msum[(size_t)N_NODES * 160];  // scatter-add accumulator (fp16)
__device__ float g_cnt[N_NODES];                  // in-degree
__device__ float g_tw[N_NODES];                   // gate
__device__ float g_bias320[320];                  // [bm | 0]

// bf16 hi/lo pre-split GEMM A operands
__device__ __align__(16) __nv_bfloat16 g_ah[(size_t)NROWS_PAD * 128], g_al[(size_t)NROWS_PAD * 128];   // node_features
__device__ __align__(16) __nv_bfloat16 g_hh[(size_t)NROWS_PAD * 192], g_hl[(size_t)NROWS_PAD * 192];   // h (K=160 pad 192)
__device__ __align__(16) __nv_bfloat16 g_uh[(size_t)NROWS_PAD * 320], g_ul[(size_t)NROWS_PAD * 320];   // U=[h|msg]

// bf16 hi/lo split weights (zero-padded K)
__device__ __align__(16) __nv_bfloat16 g_weh[128 * 128], g_wel[128 * 128];   // encoder
__device__ __align__(16) __nv_bfloat16 g_wmh[320 * 192], g_wml[320 * 192];   // message
__device__ __align__(16) __nv_bfloat16 g_wuh[160 * 320], g_wul[160 * 320];   // update
__device__ __align__(16) __nv_bfloat16 g_woh[128 * 192], g_wol[128 * 192];   // output

// ================= helpers =================
__device__ __forceinline__ uint32_t smem_u32(const void* p) {
    uint32_t a;
    asm("{ .reg .u64 t; cvta.to.shared.u64 t, %1; cvt.u32.u64 %0, t; }" : "=r"(a) : "l"(p));
    return a;
}
#define SWZ128(o) ((o) ^ (((o) >> 3) & 0x70))

__device__ __forceinline__ void cpa16(uint32_t dst, const void* src) {
    asm volatile("cp.async.cg.shared.global [%0], [%1], 16;" :: "r"(dst), "l"(src));
}
#define CP_COMMIT() asm volatile("cp.async.commit_group;" ::: "memory")
#define CP_WAIT0()  asm volatile("cp.async.wait_group 0;" ::: "memory")

__device__ __forceinline__ void ldsm4(uint32_t* r, uint32_t addr) {
    asm volatile("ldmatrix.sync.aligned.m8n8.x4.shared.b16 {%0,%1,%2,%3}, [%4];"
        : "=r"(r[0]), "=r"(r[1]), "=r"(r[2]), "=r"(r[3]) : "r"(addr));
}
__device__ __forceinline__ void ldsm2(uint32_t* r, uint32_t addr) {
    asm volatile("ldmatrix.sync.aligned.m8n8.x2.shared.b16 {%0,%1}, [%2];"
        : "=r"(r[0]), "=r"(r[1]) : "r"(addr));
}
__device__ __forceinline__ void mma16816(float* d, const uint32_t* a, const uint32_t* b) {
    asm volatile("mma.sync.aligned.m16n8k16.row.col.f32.bf16.bf16.f32 "
        "{%0,%1,%2,%3},{%4,%5,%6,%7},{%8,%9},{%0,%1,%2,%3};"
        : "+f"(d[0]), "+f"(d[1]), "+f"(d[2]), "+f"(d[3])
        : "r"(a[0]), "r"(a[1]), "r"(a[2]), "r"(a[3]), "r"(b[0]), "r"(b[1]));
}
__device__ __forceinline__ void split2(float a, float b, uint32_t& hi, uint32_t& lo) {
    __nv_bfloat16 ha = __float2bfloat16(a), hb = __float2bfloat16(b);
    __nv_bfloat16 la = __float2bfloat16(a - __bfloat162float(ha));
    __nv_bfloat16 lb = __float2bfloat16(b - __bfloat162float(hb));
    hi = (uint32_t)__bfloat16_as_ushort(ha) | ((uint32_t)__bfloat16_as_ushort(hb) << 16);
    lo = (uint32_t)__bfloat16_as_ushort(la) | ((uint32_t)__bfloat16_as_ushort(lb) << 16);
}
__device__ __forceinline__ void st_split1(__nv_bfloat16* H, __nv_bfloat16* L, size_t idx, float v) {
    __nv_bfloat16 h = __float2bfloat16(v);
    H[idx] = h;
    L[idx] = __float2bfloat16(v - __bfloat162float(h));
}
__device__ __forceinline__ void st_split4(__nv_bfloat16* H, __nv_bfloat16* L, size_t idx, float4 v) {
    uint2 hp, lp;
    split2(v.x, v.y, hp.x, lp.x);
    split2(v.z, v.w, hp.y, lp.y);
    *(uint2*)(H + idx) = hp;
    *(uint2*)(L + idx) = lp;
}
__device__ __forceinline__ float wsum(float v) {
#pragma unroll
    for (int o = 16; o; o >>= 1) v += __shfl_xor_sync(0xffffffffu, v, o);
    return v;
}
// fp16x2 vector reduction: 8 half channels per op
__device__ __forceinline__ void red8h(__half* p, float4 a, float4 b) {
    __half2 h0 = __floats2half2_rn(a.x, a.y);
    __half2 h1 = __floats2half2_rn(a.z, a.w);
    __half2 h2 = __floats2half2_rn(b.x, b.y);
    __half2 h3 = __floats2half2_rn(b.z, b.w);
    asm volatile("red.global.add.noftz.v4.f16x2 [%0], {%1,%2,%3,%4};"
                 :: "l"(p),
                    "r"(*(uint32_t*)&h0), "r"(*(uint32_t*)&h1),
                    "r"(*(uint32_t*)&h2), "r"(*(uint32_t*)&h3) : "memory");
}

// ================= tensor-core GEMM (mma.sync bf16x3 split), M64 tiles, occ 3 =====
// D[64, NT] tile = X[64, KPAD] @ W[NT, KPAD]^T (pre-split bf16 hi/lo operands).  EPI:
//   0: bias + store fp16 to g_AB (+n0 col offset, stride 320)         (message precompute)
//   1: bias + LN(NT)+relu -> Y cols 0..127 (ldy) + g_hh/g_hl split; time enc col 128+lane
//   2: bias + LN(NT)+relu + gate blend into w0 + g_hh/g_hl split (node update)
//   3: bias + row L2-normalize -> Y (output projection)
template<int NT, int KPAD, int EPI>
__global__ __launch_bounds__(256, 3) void gemm_tc(
    const __nv_bfloat16* __restrict__ Xh, const __nv_bfloat16* __restrict__ Xl,
    const __nv_bfloat16* __restrict__ Wh, const __nv_bfloat16* __restrict__ Wl,
    const float* __restrict__ bias,
    float* __restrict__ Y, int ldy,
    const float* __restrict__ a0, const float* __restrict__ a1,
    const float* __restrict__ a2, const float* __restrict__ a3,
    const float* __restrict__ a4, const float* __restrict__ a5,
    const float* __restrict__ a6,
    float* __restrict__ w0)
{
    extern __shared__ __align__(16) char dsm[];
    char* base = (char*)((((uintptr_t)dsm) + 1023) & ~(uintptr_t)1023);
    const uint32_t sb = smem_u32(base);
    constexpr int A_HI = 0, A_LO = 8192, B_HI = 16384;
    constexpr int B_LO = 16384 + NT * 128;
    constexpr int NW = NT / 4;          // cols per warp (warp grid 2 x 4)
    constexpr int NTILES = NW / 8;      // 5 for NT=160, 4 for NT=128
    const int tid = threadIdx.x, wid = tid >> 5, lane = tid & 31;
    const int wm = wid & 1, wn = wid >> 1;
    const int bm0 = blockIdx.y * 64, n0 = blockIdx.x * NT;

    float acc[2][NTILES][4];
#pragma unroll
    for (int m = 0; m < 2; m++)
#pragma unroll
        for (int t = 0; t < NTILES; t++)
#pragma unroll
            for (int j = 0; j < 4; j++) acc[m][t][j] = 0.f;

    constexpr int NCHUNK = KPAD / 64;
    for (int ch = 0; ch < NCHUNK; ch++) {
        const int c0 = ch * 64;
#pragma unroll
        for (int s = tid; s < 64 * 8; s += 256) {
            int r = s >> 3, i = s & 7;
            uint32_t off = SWZ128((uint32_t)(r * 128 + i * 16));
            cpa16(sb + A_HI + off, Xh + (size_t)(bm0 + r) * KPAD + c0 + i * 8);
            cpa16(sb + A_LO + off, Xl + (size_t)(bm0 + r) * KPAD + c0 + i * 8);
        }
        for (int s = tid; s < NT * 8; s += 256) {
            int r = s >> 3, i = s & 7;
            uint32_t off = SWZ128((uint32_t)(r * 128 + i * 16));
            cpa16(sb + B_HI + off, Wh + (size_t)(n0 + r) * KPAD + c0 + i * 8);
            cpa16(sb + B_LO + off, Wl + (size_t)(n0 + r) * KPAD + c0 + i * 8);
        }
        CP_COMMIT();
        CP_WAIT0();
        __syncthreads();

#pragma unroll
        for (int ks = 0; ks < 4; ks++) {
            uint32_t ah[2][4], al[2][4];
            const int arow = wm * 32 + (lane & 15);
            const int akb = ks * 32 + ((lane >> 4) << 4);
            {
                uint32_t o0 = SWZ128((uint32_t)(arow * 128 + akb));
                ldsm4(ah[0], sb + A_HI + o0);
                ldsm4(al[0], sb + A_LO + o0);
                uint32_t o1 = SWZ128((uint32_t)((arow + 16) * 128 + akb));
                ldsm4(ah[1], sb + A_HI + o1);
                ldsm4(al[1], sb + A_LO + o1);
            }
            const int q = lane >> 3;
            const int browb = wn * NW + ((q >> 1) << 3) + (lane & 7);
            const int bkb = ks * 32 + (q & 1) * 16;
#pragma unroll
            for (int nt = 0; nt + 1 < NTILES; nt += 2) {
                uint32_t bo = SWZ128((uint32_t)((browb + nt * 8) * 128 + bkb));
                uint32_t bh4[4], bl4[4];
                ldsm4(bh4, sb + B_HI + bo);
                ldsm4(bl4, sb + B_LO + bo);
                mma16816(acc[0][nt], ah[0], bh4);
                mma16816(acc[0][nt], ah[0], bl4);
                mma16816(acc[0][nt], al[0], bh4);
                mma16816(acc[1][nt], ah[1], bh4);
                mma16816(acc[1][nt], ah[1], bl4);
                mma16816(acc[1][nt], al[1], bh4);
                mma16816(acc[0][nt + 1], ah[0], bh4 + 2);
                mma16816(acc[0][nt + 1], ah[0], bl4 + 2);
                mma16816(acc[0][nt + 1], al[0], bh4 + 2);
                mma16816(acc[1][nt + 1], ah[1], bh4 + 2);
                mma16816(acc[1][nt + 1], ah[1], bl4 + 2);
                mma16816(acc[1][nt + 1], al[1], bh4 + 2);
            }
            if (NTILES & 1) {
                constexpr int ntl = NTILES - 1;
                const int browt = wn * NW + ntl * 8 + (lane & 7);
                const int bkt = ks * 32 + ((lane >> 3) & 1) * 16;
                uint32_t bo = SWZ128((uint32_t)(browt * 128 + bkt));
                uint32_t bh2[2], bl2[2];
                ldsm2(bh2, sb + B_HI + bo);
                ldsm2(bl2, sb + B_LO + bo);
                mma16816(acc[0][ntl], ah[0], bh2);
                mma16816(acc[0][ntl], ah[0], bl2);
                mma16816(acc[0][ntl], al[0], bh2);
                mma16816(acc[1][ntl], ah[1], bh2);
                mma16816(acc[1][ntl], ah[1], bl2);
                mma16816(acc[1][ntl], al[1], bh2);
            }
        }
        __syncthreads();
    }

    // ---------------- stage D in SMEM (reuse buffers), row-wise epilogue ----------
    float* Dsm = (float*)base;   // [64][NT]
#pragma unroll
    for (int mb = 0; mb < 2; mb++) {
        const int r0 = wm * 32 + mb * 16 + (lane >> 2);
        const int c0 = wn * NW + (lane & 3) * 2;
#pragma unroll
        for (int nt = 0; nt < NTILES; nt++) {
            *(float2*)&Dsm[r0 * NT + c0 + nt * 8] = make_float2(acc[mb][nt][0], acc[mb][nt][1]);
            *(float2*)&Dsm[(r0 + 8) * NT + c0 + nt * 8] = make_float2(acc[mb][nt][2], acc[mb][nt][3]);
        }
    }
    __syncthreads();

    constexpr int NJ = NT / 32;
    for (int rr = 0; rr < 8; rr++) {
        const int r = wid * 8 + rr;
        const int gr = bm0 + r;
        const bool rv = gr < N_NODES;
        float v[NJ];
#pragma unroll
        for (int j = 0; j < NJ; j++) {
            int c = lane + 32 * j;
            v[j] = Dsm[r * NT + c] + bias[(EPI == 0 ? n0 : 0) + c];
        }

        if (EPI == 0) {
            if (rv) {
#pragma unroll
                for (int j = 0; j < NJ; j++)
                    g_AB[(size_t)gr * 320 + n0 + lane + 32 * j] = __float2half(v[j]);
            }
        } else if (EPI == 1 || EPI == 2) {
            float s = 0.f, q = 0.f;
#pragma unroll
            for (int j = 0; j < NJ; j++) { s += v[j]; q += v[j] * v[j]; }
            float mean = wsum(s) * (1.f / NT);
            float var = wsum(q) * (1.f / NT) - mean * mean;
            float rstd = rsqrtf(var + LN_EPS);
            if (rv) {
                if (EPI == 1) {
#pragma unroll
                    for (int j = 0; j < NJ; j++) {
                        int c = lane + 32 * j;
                        float hv = fmaxf(0.f, (v[j] - mean) * rstd * a0[c] + a1[c]);
                        Y[(size_t)gr * ldy + c] = hv;
                        st_split1(g_hh, g_hl, (size_t)gr * 192 + c, hv);
                    }
                    float t0 = a2[gr];
                    float tv = t0 * a3[lane] + a4[lane];
                    float tm = wsum(tv) * (1.f / 32.f);
                    float td = tv - tm;
                    float tvar = wsum(td * td) * (1.f / 32.f);
                    float tr = rsqrtf(tvar + LN_EPS);
                    float to = fmaxf(0.f, td * tr * a5[lane] + a6[lane]);
                    Y[(size_t)gr * ldy + 128 + lane] = to;
                    st_split1(g_hh, g_hl, (size_t)gr * 192 + 128 + lane, to);
                    g_hh[(size_t)gr * 192 + 160 + lane] = __float2bfloat16(0.f);
                    g_hl[(size_t)gr * 192 + 160 + lane] = __float2bfloat16(0.f);
                } else {
                    float tw = a2[gr];
#pragma unroll
                    for (int j = 0; j < NJ; j++) {
                        int c = lane + 32 * j;
                        float hn = fmaxf(0.f, (v[j] - mean) * rstd * a0[c] + a1[c]);
                        float ho = w0[(size_t)gr * 160 + c];
                        float hv = tw * hn + (1.f - tw) * ho;
                        w0[(size_t)gr * 160 + c] = hv;
                        st_split1(g_hh, g_hl, (size_t)gr * 192 + c, hv);
                    }
                    g_hh[(size_t)gr * 192 + 160 + lane] = __float2bfloat16(0.f);
                    g_hl[(size_t)gr * 192 + 160 + lane] = __float2bfloat16(0.f);
                }
            }
        } else {  // EPI == 3
            float q = 0.f;
#pragma unroll
            for (int j = 0; j < NJ; j++) q += v[j] * v[j];
            float sc = 1.f / fmaxf(sqrtf(wsum(q)), 1e-12f);
            if (rv) {
#pragma unroll
                for (int j = 0; j < NJ; j++)
                    Y[(size_t)gr * ldy + lane + 32 * j] = v[j] * sc;
            }
        }
    }
}

// ================= weight / input split kernels =================
__global__ void split_w(const float* __restrict__ W, __nv_bfloat16* __restrict__ H,
                        __nv_bfloat16* __restrict__ L, int NR, int K, int KPAD) {
    int t = blockIdx.x * blockDim.x + threadIdx.x;
    if (t >= NR * KPAD) return;
    int r = t / KPAD, c = t - r * KPAD;
    float v = (c < K) ? W[r * K + c] : 0.f;
    __nv_bfloat16 h = __float2bfloat16(v);
    H[t] = h;
    L[t] = __float2bfloat16(v - __bfloat162float(h));
}
__global__ void split_msg(const float* __restrict__ wm, const float* __restrict__ bm) {
    int t = blockIdx.x * blockDim.x + threadIdx.x;
    if (t < 320 * 192) {
        int r = t / 192, c = t - r * 192;
        float v = 0.f;
        if (c < 160) v = (r < 160) ? wm[r * 320 + c] : wm[(r - 160) * 320 + 160 + c];
        __nv_bfloat16 h = __float2bfloat16(v);
        g_wmh[t] = h;
        g_wml[t] = __float2bfloat16(v - __bfloat162float(h));
    }
    if (t < 320) g_bias320[t] = (t < 160) ? bm[t] : 0.f;
}

// ================= zero / degree =================
__global__ void zero_cnt() {
    int i = blockIdx.x * blockDim.x + threadIdx.x;
    if (i < N_NODES) g_cnt[i] = 0.f;
}
__global__ void zero_msum() {
    int i = blockIdx.x * blockDim.x + threadIdx.x;
    int st = gridDim.x * blockDim.x;
    uint4* p = (uint4*)g_msum;
    const int n4 = N_NODES * 20;   // 160 halves = 20 uint4 per node
    uint4 z = make_uint4(0, 0, 0, 0);
    for (int k = i; k < n4; k += st) p[k] = z;
}
__global__ void degree_kernel(const int* __restrict__ ei) {
    int e = blockIdx.x * blockDim.x + threadIdx.x;
    if (e < N_EDGES) atomicAdd(&g_cnt[ei[N_EDGES + e]], 1.0f);
}

// ================= edge pass (fp16 gather, fp16x2 vector-reduction scatter) ========
__global__ void edge_kernel(const int* __restrict__ ei, const float* __restrict__ ew,
                            const float* __restrict__ gmv, const float* __restrict__ bemv)
{
    int w = (blockIdx.x * blockDim.x + threadIdx.x) >> 5;
    int lane = threadIdx.x & 31;
    if (w >= N_EDGES) return;
    int src = ei[w];
    int dst = ei[N_EDGES + w];
    float ewt = ew[w];
    const bool act = lane < 20;

    float v[8];
#pragma unroll
    for (int k = 0; k < 8; k++) v[k] = 0.f;
    if (act) {
        uint4 sv = *(const uint4*)(g_AB + (size_t)src * 320 + lane * 8);
        uint4 dv = *(const uint4*)(g_AB + (size_t)dst * 320 + 160 + lane * 8);
        const __half2* sh = (const __half2*)&sv;
        const __half2* dh = (const __half2*)&dv;
#pragma unroll
        for (int k = 0; k < 4; k++) {
            float2 a = __half22float2(sh[k]);
            float2 b = __half22float2(dh[k]);
            v[2 * k + 0] = a.x + b.x;
            v[2 * k + 1] = a.y + b.y;
        }
    }

    float s = 0.f;
#pragma unroll
    for (int k = 0; k < 8; k++) s += v[k];
    float mean = wsum(s) * (1.0f / 160.0f);

    float q = 0.f;
    if (act) {
#pragma unroll
        for (int k = 0; k < 8; k++) q += (v[k] - mean) * (v[k] - mean);
    }
    float var = wsum(q) * (1.0f / 160.0f);
    float rstd = rsqrtf(var + LN_EPS);

    if (act) {
        const int c0 = lane * 8;
        float4 g0 = ((const float4*)gmv)[2 * lane];
        float4 g1 = ((const float4*)gmv)[2 * lane + 1];
        float4 b0 = ((const float4*)bemv)[2 * lane];
        float4 b1 = ((const float4*)bemv)[2 * lane + 1];
        float4 o0, o1;
        o0.x = fmaxf(0.f, (v[0] - mean) * rstd * g0.x + b0.x) * ewt;
        o0.y = fmaxf(0.f, (v[1] - mean) * rstd * g0.y + b0.y) * ewt;
        o0.z = fmaxf(0.f, (v[2] - mean) * rstd * g0.z + b0.z) * ewt;
        o0.w = fmaxf(0.f, (v[3] - mean) * rstd * g0.w + b0.w) * ewt;
        o1.x = fmaxf(0.f, (v[4] - mean) * rstd * g1.x + b1.x) * ewt;
        o1.y = fmaxf(0.f, (v[5] - mean) * rstd * g1.y + b1.y) * ewt;
        o1.z = fmaxf(0.f, (v[6] - mean) * rstd * g1.z + b1.z) * ewt;
        o1.w = fmaxf(0.f, (v[7] - mean) * rstd * g1.w + b1.w) * ewt;
        red8h(g_msum + (size_t)dst * 160 + c0, o0, o1);
    }
}

// ================= node pass 1: U=[h|messages] split to bf16, gate tw =============
__global__ void node1_kernel(const float* __restrict__ wgv, const float* __restrict__ bgv) {
    int n = (blockIdx.x * blockDim.x + threadIdx.x) >> 5;
    int lane = threadIdx.x & 31;
    if (n >= N_NODES) return;

    float c = g_cnt[n];
    float inv = (c > 0.f) ? 1.f / (c + 1e-8f) : 0.f;

    const float4* H = (const float4*)(g_h + (size_t)n * 160);
    const __half* Mbase = g_msum + (size_t)n * 160;
    const bool two = lane < 8;
    const size_t ub = (size_t)n * 320;

    float dotp = 0.f;
    {
        float4 h = H[lane];
        st_split4(g_uh, g_ul, ub + 4 * lane, h);
        uint2 mraw = *(const uint2*)(Mbase + 4 * lane);
        float2 f0 = __half22float2(*(const __half2*)&mraw.x);
        float2 f1 = __half22float2(*(const __half2*)&mraw.y);
        float4 mm = make_float4(f0.x * inv, f0.y * inv, f1.x * inv, f1.y * inv);
        st_split4(g_uh, g_ul, ub + 160 + 4 * lane, mm);
        float4 wg = ((const float4*)wgv)[lane];
        dotp = h.x * wg.x + h.y * wg.y + h.z * wg.z + h.w * wg.w;
    }
    if (two) {
        float4 h = H[lane + 32];
        st_split4(g_uh, g_ul, ub + 128 + 4 * lane, h);
        uint2 mraw = *(const uint2*)(Mbase + 128 + 4 * lane);
        float2 f0 = __half22float2(*(const __half2*)&mraw.x);
        float2 f1 = __half22float2(*(const __half2*)&mraw.y);
        float4 mm = make_float4(f0.x * inv, f0.y * inv, f1.x * inv, f1.y * inv);
        st_split4(g_uh, g_ul, ub + 160 + 128 + 4 * lane, mm);
        float4 wg = ((const float4*)wgv)[lane + 32];
        dotp += h.x * wg.x + h.y * wg.y + h.z * wg.z + h.w * wg.w;
    }
    float tot = wsum(dotp);
    if (lane == 0) g_tw[n] = 1.f / (1.f + expf(-(tot + bgv[0])));
}

// ================= host orchestration =================
extern "C" void kernel_launch(void* const* d_in, const int* in_sizes, int n_in,
                              void* d_out, int out_size)
{
    const float* node_features = (const float*)d_in[0];
    const int*   edge_index    = (const int*)d_in[1];
    const float* edge_weights  = (const float*)d_in[2];
    const float* time_steps    = (const float*)d_in[3];
    const float* w_enc   = (const float*)d_in[4];
    const float* b_enc   = (const float*)d_in[5];
    const float* g_enc   = (const float*)d_in[6];
    const float* be_enc  = (const float*)d_in[7];
    const float* w_time  = (const float*)d_in[8];
    const float* b_time  = (const float*)d_in[9];
    const float* g_time  = (const float*)d_in[10];
    const float* be_time = (const float*)d_in[11];
    const float* wm  = (const float*)d_in[12];
    const float* bm  = (const float*)d_in[13];
    const float* gm  = (const float*)d_in[14];
    const float* bem = (const float*)d_in[15];
    const float* wu  = (const float*)d_in[16];
    const float* bu  = (const float*)d_in[17];
    const float* gu  = (const float*)d_in[18];
    const float* beu = (const float*)d_in[19];
    const float* wg  = (const float*)d_in[20];
    const float* bg  = (const float*)d_in[21];
    const float* w_out = (const float*)d_in[22];
    const float* b_out = (const float*)d_in[23];
    float* out = (float*)d_out;

    float *p_h, *p_tw, *p_b320;
    __nv_bfloat16 *p_ah, *p_al, *p_hh, *p_hl, *p_uh, *p_ul;
    __nv_bfloat16 *p_weh, *p_wel, *p_wmh, *p_wml, *p_wuh, *p_wul, *p_woh, *p_wol;
    cudaGetSymbolAddress((void**)&p_h, g_h);
    cudaGetSymbolAddress((void**)&p_tw, g_tw);
    cudaGetSymbolAddress((void**)&p_b320, g_bias320);
    cudaGetSymbolAddress((void**)&p_ah, g_ah);
    cudaGetSymbolAddress((void**)&p_al, g_al);
    cudaGetSymbolAddress((void**)&p_hh, g_hh);
    cudaGetSymbolAddress((void**)&p_hl, g_hl);
    cudaGetSymbolAddress((void**)&p_uh, g_uh);
    cudaGetSymbolAddress((void**)&p_ul, g_ul);
    cudaGetSymbolAddress((void**)&p_weh, g_weh);
    cudaGetSymbolAddress((void**)&p_wel, g_wel);
    cudaGetSymbolAddress((void**)&p_wmh, g_wmh);
    cudaGetSymbolAddress((void**)&p_wml, g_wml);
    cudaGetSymbolAddress((void**)&p_wuh, g_wuh);
    cudaGetSymbolAddress((void**)&p_wul, g_wul);
    cudaGetSymbolAddress((void**)&p_woh, g_woh);
    cudaGetSymbolAddress((void**)&p_wol, g_wol);

    const int GBM = (N_NODES + 63) / 64;                     // 1563 row-tiles (M64)
    const int NODE_WARP_BLOCKS = (N_NODES * 32 + 255) / 256; // 12500
    const int EDGE_WARP_BLOCKS = (N_EDGES * 32 + 255) / 256; // 100000

    const int SM160 = 16384 + 160 * 256 + 1024;   // 58368 (Dsm 40KB overlays)
    const int SM128 = 16384 + 128 * 256 + 1024;   // 50176 (Dsm 32KB overlays)
    cudaFuncSetAttribute(gemm_tc<128, 128, 1>, cudaFuncAttributeMaxDynamicSharedMemorySize, SM128);
    cudaFuncSetAttribute(gemm_tc<160, 192, 0>, cudaFuncAttributeMaxDynamicSharedMemorySize, SM160);
    cudaFuncSetAttribute(gemm_tc<160, 320, 2>, cudaFuncAttributeMaxDynamicSharedMemorySize, SM160);
    cudaFuncSetAttribute(gemm_tc<128, 192, 3>, cudaFuncAttributeMaxDynamicSharedMemorySize, SM128);

    // degrees (constant across layers)
    zero_cnt<<<(N_NODES + 255) / 256, 256>>>();
    degree_kernel<<<(N_EDGES + 255) / 256, 256>>>(edge_index);

    // split inputs/weights for encoder
    split_w<<<(N_NODES * 128 + 255) / 256, 256>>>(node_features, p_ah, p_al, N_NODES, 128, 128);
    split_w<<<(128 * 128 + 255) / 256, 256>>>(w_enc, p_weh, p_wel, 128, 128, 128);
    gemm_tc<128, 128, 1><<<dim3(1, GBM), 256, SM128>>>(
        p_ah, p_al, p_weh, p_wel, b_enc, p_h, 160,
        g_enc, be_enc, time_steps, w_time, b_time, g_time, be_time, nullptr);

    for (int l = 0; l < 2; l++) {
        split_msg<<<(320 * 192 + 255) / 256, 256>>>(wm + (size_t)l * 160 * 320, bm + l * 160);
        gemm_tc<160, 192, 0><<<dim3(2, GBM), 256, SM160>>>(
            p_hh, p_hl, p_wmh, p_wml, p_b320, nullptr, 0,
            nullptr, nullptr, nullptr, nullptr, nullptr, nullptr, nullptr, nullptr);
        zero_msum<<<4096, 256>>>();
        edge_kernel<<<EDGE_WARP_BLOCKS, 256>>>(edge_index, edge_weights, gm + l * 160, bem + l * 160);
        node1_kernel<<<NODE_WARP_BLOCKS, 256>>>(wg + l * 160, bg + l);
        split_w<<<(160 * 320 + 255) / 256, 256>>>(wu + (size_t)l * 160 * 320, p_wuh, p_wul, 160, 320, 320);
        gemm_tc<160, 320, 2><<<dim3(1, GBM), 256, SM160>>>(
            p_uh, p_ul, p_wuh, p_wul, bu + l * 160, nullptr, 0,
            gu + l * 160, beu + l * 160, p_tw, nullptr, nullptr, nullptr, nullptr, p_h);
    }

    split_w<<<(128 * 192 + 255) / 256, 256>>>(w_out, p_woh, p_wol, 128, 160, 192);
    gemm_tc<128, 192, 3><<<dim3(1, GBM), 256, SM128>>>(
        p_hh, p_hl, p_woh, p_wol, b_out, out, 128,
        nullptr, nullptr, nullptr, nullptr, nullptr, nullptr, nullptr, nullptr);
}

// round 16
// speedup vs baseline: 1.6682x; 1.0405x over previous
#include <cuda_runtime.h>
#include <cuda_bf16.h>
#include <cuda_fp16.h>
#include <math.h>
#include <stdint.h>

#define N_NODES 100000
#define NROWS_PAD 100096          // >= 1563 * 64
#define N_EDGES 800000
#define LN_EPS 1e-5f

// ================= scratch (device globals; no allocation allowed) =================
__device__ float g_h[(size_t)N_NODES * 160];      // node state fp32
__device__ __half g_AB[(size_t)NROWS_PAD * 320];  // message A|B fp16 (L2-resident)
__device__ __half g_msum[(size_t)N_NODES * 160];  // scatter-add accumulator (fp16)
__device__ float g_cnt[N_NODES];                  // in-degree
__device__ float g_tw[N_NODES];                   // gate
__device__ float g_bias320[320];                  // [bm | 0]

// bf16 hi/lo pre-split GEMM A operands
__device__ __align__(16) __nv_bfloat16 g_ah[(size_t)NROWS_PAD * 128], g_al[(size_t)NROWS_PAD * 128];   // node_features
__device__ __align__(16) __nv_bfloat16 g_hh[(size_t)NROWS_PAD * 160], g_hl[(size_t)NROWS_PAD * 160];   // h (K=160, no pad)
__device__ __align__(16) __nv_bfloat16 g_uh[(size_t)NROWS_PAD * 320], g_ul[(size_t)NROWS_PAD * 320];   // U=[h|msg]

// bf16 hi/lo split weights
__device__ __align__(16) __nv_bfloat16 g_weh[128 * 128], g_wel[128 * 128];   // encoder
__device__ __align__(16) __nv_bfloat16 g_wmh[320 * 160], g_wml[320 * 160];   // message (K=160)
__device__ __align__(16) __nv_bfloat16 g_wuh[160 * 320], g_wul[160 * 320];   // update
__device__ __align__(16) __nv_bfloat16 g_woh[128 * 160], g_wol[128 * 160];   // output (K=160)

// ================= helpers =================
__device__ __forceinline__ uint32_t smem_u32(const void* p) {
    uint32_t a;
    asm("{ .reg .u64 t; cvta.to.shared.u64 t, %1; cvt.u32.u64 %0, t; }" : "=r"(a) : "l"(p));
    return a;
}
#define SWZ128(o) ((o) ^ (((o) >> 3) & 0x70))

__device__ __forceinline__ void cpa16(uint32_t dst, const void* src) {
    asm volatile("cp.async.cg.shared.global [%0], [%1], 16;" :: "r"(dst), "l"(src));
}
#define CP_COMMIT() asm volatile("cp.async.commit_group;" ::: "memory")
#define CP_WAIT0()  asm volatile("cp.async.wait_group 0;" ::: "memory")

__device__ __forceinline__ void ldsm4(uint32_t* r, uint32_t addr) {
    asm volatile("ldmatrix.sync.aligned.m8n8.x4.shared.b16 {%0,%1,%2,%3}, [%4];"
        : "=r"(r[0]), "=r"(r[1]), "=r"(r[2]), "=r"(r[3]) : "r"(addr));
}
__device__ __forceinline__ void ldsm2(uint32_t* r, uint32_t addr) {
    asm volatile("ldmatrix.sync.aligned.m8n8.x2.shared.b16 {%0,%1}, [%2];"
        : "=r"(r[0]), "=r"(r[1]) : "r"(addr));
}
__device__ __forceinline__ void mma16816(float* d, const uint32_t* a, const uint32_t* b) {
    asm volatile("mma.sync.aligned.m16n8k16.row.col.f32.bf16.bf16.f32 "
        "{%0,%1,%2,%3},{%4,%5,%6,%7},{%8,%9},{%0,%1,%2,%3};"
        : "+f"(d[0]), "+f"(d[1]), "+f"(d[2]), "+f"(d[3])
        : "r"(a[0]), "r"(a[1]), "r"(a[2]), "r"(a[3]), "r"(b[0]), "r"(b[1]));
}
__device__ __forceinline__ void split2(float a, float b, uint32_t& hi, uint32_t& lo) {
    __nv_bfloat16 ha = __float2bfloat16(a), hb = __float2bfloat16(b);
    __nv_bfloat16 la = __float2bfloat16(a - __bfloat162float(ha));
    __nv_bfloat16 lb = __float2bfloat16(b - __bfloat162float(hb));
    hi = (uint32_t)__bfloat16_as_ushort(ha) | ((uint32_t)__bfloat16_as_ushort(hb) << 16);
    lo = (uint32_t)__bfloat16_as_ushort(la) | ((uint32_t)__bfloat16_as_ushort(lb) << 16);
}
__device__ __forceinline__ void st_split1(__nv_bfloat16* H, __nv_bfloat16* L, size_t idx, float v) {
    __nv_bfloat16 h = __float2bfloat16(v);
    H[idx] = h;
    L[idx] = __float2bfloat16(v - __bfloat162float(h));
}
__device__ __forceinline__ void st_split4(__nv_bfloat16* H, __nv_bfloat16* L, size_t idx, float4 v) {
    uint2 hp, lp;
    split2(v.x, v.y, hp.x, lp.x);
    split2(v.z, v.w, hp.y, lp.y);
    *(uint2*)(H + idx) = hp;
    *(uint2*)(L + idx) = lp;
}
__device__ __forceinline__ float wsum(float v) {
#pragma unroll
    for (int o = 16; o; o >>= 1) v += __shfl_xor_sync(0xffffffffu, v, o);
    return v;
}
// fp16x2 vector reduction: 8 half channels per op
__device__ __forceinline__ void red8h(__half* p, float4 a, float4 b) {
    __half2 h0 = __floats2half2_rn(a.x, a.y);
    __half2 h1 = __floats2half2_rn(a.z, a.w);
    __half2 h2 = __floats2half2_rn(b.x, b.y);
    __half2 h3 = __floats2half2_rn(b.z, b.w);
    asm volatile("red.global.add.noftz.v4.f16x2 [%0], {%1,%2,%3,%4};"
                 :: "l"(p),
                    "r"(*(uint32_t*)&h0), "r"(*(uint32_t*)&h1),
                    "r"(*(uint32_t*)&h2), "r"(*(uint32_t*)&h3) : "memory");
}

// ================= tensor-core GEMM (mma.sync bf16x3 split), M64 tiles, occ 3 =====
// D[64, NT] tile = X[64, KPAD] @ W[NT, KPAD]^T.  KPAD may be a 32-multiple (tail chunk
// handled via compile-time guards).  EPI:
//   0: bias + store fp16 to g_AB (+n0 col offset, stride 320)         (message precompute)
//   1: bias + LN(NT)+relu -> Y cols 0..127 (ldy) + g_hh/g_hl split; time enc col 128+lane
//   2: bias + LN(NT)+relu + gate blend into w0 + g_hh/g_hl split (node update)
//   3: bias + row L2-normalize -> Y (output projection)
template<int NT, int KPAD, int EPI>
__global__ __launch_bounds__(256, 3) void gemm_tc(
    const __nv_bfloat16* __restrict__ Xh, const __nv_bfloat16* __restrict__ Xl,
    const __nv_bfloat16* __restrict__ Wh, const __nv_bfloat16* __restrict__ Wl,
    const float* __restrict__ bias,
    float* __restrict__ Y, int ldy,
    const float* __restrict__ a0, const float* __restrict__ a1,
    const float* __restrict__ a2, const float* __restrict__ a3,
    const float* __restrict__ a4, const float* __restrict__ a5,
    const float* __restrict__ a6,
    float* __restrict__ w0)
{
    extern __shared__ __align__(16) char dsm[];
    char* base = (char*)((((uintptr_t)dsm) + 1023) & ~(uintptr_t)1023);
    const uint32_t sb = smem_u32(base);
    constexpr int A_HI = 0, A_LO = 8192, B_HI = 16384;
    constexpr int B_LO = 16384 + NT * 128;
    constexpr int NW = NT / 4;          // cols per warp (warp grid 2 x 4)
    constexpr int NTILES = NW / 8;      // 5 for NT=160, 4 for NT=128
    const int tid = threadIdx.x, wid = tid >> 5, lane = tid & 31;
    const int wm = wid & 1, wn = wid >> 1;
    const int bm0 = blockIdx.y * 64, n0 = blockIdx.x * NT;

    float acc[2][NTILES][4];
#pragma unroll
    for (int m = 0; m < 2; m++)
#pragma unroll
        for (int t = 0; t < NTILES; t++)
#pragma unroll
            for (int j = 0; j < 4; j++) acc[m][t][j] = 0.f;

    constexpr int NCHUNK = (KPAD + 63) / 64;
#pragma unroll
    for (int ch = 0; ch < NCHUNK; ch++) {
        const int c0 = ch * 64;
#pragma unroll
        for (int s = tid; s < 64 * 8; s += 256) {
            int r = s >> 3, i = s & 7;
            if (c0 + (i & 7) * 8 < KPAD) {
                uint32_t off = SWZ128((uint32_t)(r * 128 + i * 16));
                cpa16(sb + A_HI + off, Xh + (size_t)(bm0 + r) * KPAD + c0 + i * 8);
                cpa16(sb + A_LO + off, Xl + (size_t)(bm0 + r) * KPAD + c0 + i * 8);
            }
        }
        for (int s = tid; s < NT * 8; s += 256) {
            int r = s >> 3, i = s & 7;
            if (c0 + i * 8 < KPAD) {
                uint32_t off = SWZ128((uint32_t)(r * 128 + i * 16));
                cpa16(sb + B_HI + off, Wh + (size_t)(n0 + r) * KPAD + c0 + i * 8);
                cpa16(sb + B_LO + off, Wl + (size_t)(n0 + r) * KPAD + c0 + i * 8);
            }
        }
        CP_COMMIT();
        CP_WAIT0();
        __syncthreads();

#pragma unroll
        for (int ks = 0; ks < 4; ks++) {
            if (c0 + ks * 16 >= KPAD) break;
            uint32_t ah[2][4], al[2][4];
            const int arow = wm * 32 + (lane & 15);
            const int akb = ks * 32 + ((lane >> 4) << 4);
            {
                uint32_t o0 = SWZ128((uint32_t)(arow * 128 + akb));
                ldsm4(ah[0], sb + A_HI + o0);
                ldsm4(al[0], sb + A_LO + o0);
                uint32_t o1 = SWZ128((uint32_t)((arow + 16) * 128 + akb));
                ldsm4(ah[1], sb + A_HI + o1);
                ldsm4(al[1], sb + A_LO + o1);
            }
            const int q = lane >> 3;
            const int browb = wn * NW + ((q >> 1) << 3) + (lane & 7);
            const int bkb = ks * 32 + (q & 1) * 16;
#pragma unroll
            for (int nt = 0; nt + 1 < NTILES; nt += 2) {
                uint32_t bo = SWZ128((uint32_t)((browb + nt * 8) * 128 + bkb));
                uint32_t bh4[4], bl4[4];
                ldsm4(bh4, sb + B_HI + bo);
                ldsm4(bl4, sb + B_LO + bo);
                mma16816(acc[0][nt], ah[0], bh4);
                mma16816(acc[0][nt], ah[0], bl4);
                mma16816(acc[0][nt], al[0], bh4);
                mma16816(acc[1][nt], ah[1], bh4);
                mma16816(acc[1][nt], ah[1], bl4);
                mma16816(acc[1][nt], al[1], bh4);
                mma16816(acc[0][nt + 1], ah[0], bh4 + 2);
                mma16816(acc[0][nt + 1], ah[0], bl4 + 2);
                mma16816(acc[0][nt + 1], al[0], bh4 + 2);
                mma16816(acc[1][nt + 1], ah[1], bh4 + 2);
                mma16816(acc[1][nt + 1], ah[1], bl4 + 2);
                mma16816(acc[1][nt + 1], al[1], bh4 + 2);
            }
            if (NTILES & 1) {
                constexpr int ntl = NTILES - 1;
                const int browt = wn * NW + ntl * 8 + (lane & 7);
                const int bkt = ks * 32 + ((lane >> 3) & 1) * 16;
                uint32_t bo = SWZ128((uint32_t)(browt * 128 + bkt));
                uint32_t bh2[2], bl2[2];
                ldsm2(bh2, sb + B_HI + bo);
                ldsm2(bl2, sb + B_LO + bo);
                mma16816(acc[0][ntl], ah[0], bh2);
                mma16816(acc[0][ntl], ah[0], bl2);
                mma16816(acc[0][ntl], al[0], bh2);
                mma16816(acc[1][ntl], ah[1], bh2);
                mma16816(acc[1][ntl], ah[1], bl2);
                mma16816(acc[1][ntl], al[1], bh2);
            }
        }
        __syncthreads();
    }

    // ---------------- stage D in SMEM (reuse buffers), row-wise epilogue ----------
    float* Dsm = (float*)base;   // [64][NT]
#pragma unroll
    for (int mb = 0; mb < 2; mb++) {
        const int r0 = wm * 32 + mb * 16 + (lane >> 2);
        const int c0 = wn * NW + (lane & 3) * 2;
#pragma unroll
        for (int nt = 0; nt < NTILES; nt++) {
            *(float2*)&Dsm[r0 * NT + c0 + nt * 8] = make_float2(acc[mb][nt][0], acc[mb][nt][1]);
            *(float2*)&Dsm[(r0 + 8) * NT + c0 + nt * 8] = make_float2(acc[mb][nt][2], acc[mb][nt][3]);
        }
    }
    __syncthreads();

    constexpr int NJ = NT / 32;
    for (int rr = 0; rr < 8; rr++) {
        const int r = wid * 8 + rr;
        const int gr = bm0 + r;
        const bool rv = gr < N_NODES;
        float v[NJ];
#pragma unroll
        for (int j = 0; j < NJ; j++) {
            int c = lane + 32 * j;
            v[j] = Dsm[r * NT + c] + bias[(EPI == 0 ? n0 : 0) + c];
        }

        if (EPI == 0) {
            if (rv) {
#pragma unroll
                for (int j = 0; j < NJ; j++)
                    g_AB[(size_t)gr * 320 + n0 + lane + 32 * j] = __float2half(v[j]);
            }
        } else if (EPI == 1 || EPI == 2) {
            float s = 0.f, q = 0.f;
#pragma unroll
            for (int j = 0; j < NJ; j++) { s += v[j]; q += v[j] * v[j]; }
            float mean = wsum(s) * (1.f / NT);
            float var = wsum(q) * (1.f / NT) - mean * mean;
            float rstd = rsqrtf(var + LN_EPS);
            if (rv) {
                if (EPI == 1) {
#pragma unroll
                    for (int j = 0; j < NJ; j++) {
                        int c = lane + 32 * j;
                        float hv = fmaxf(0.f, (v[j] - mean) * rstd * a0[c] + a1[c]);
                        Y[(size_t)gr * ldy + c] = hv;
                        st_split1(g_hh, g_hl, (size_t)gr * 160 + c, hv);
                    }
                    float t0 = a2[gr];
                    float tv = t0 * a3[lane] + a4[lane];
                    float tm = wsum(tv) * (1.f / 32.f);
                    float td = tv - tm;
                    float tvar = wsum(td * td) * (1.f / 32.f);
                    float tr = rsqrtf(tvar + LN_EPS);
                    float to = fmaxf(0.f, td * tr * a5[lane] + a6[lane]);
                    Y[(size_t)gr * ldy + 128 + lane] = to;
                    st_split1(g_hh, g_hl, (size_t)gr * 160 + 128 + lane, to);
                } else {
                    float tw = a2[gr];
#pragma unroll
                    for (int j = 0; j < NJ; j++) {
                        int c = lane + 32 * j;
                        float hn = fmaxf(0.f, (v[j] - mean) * rstd * a0[c] + a1[c]);
                        float ho = w0[(size_t)gr * 160 + c];
                        float hv = tw * hn + (1.f - tw) * ho;
                        w0[(size_t)gr * 160 + c] = hv;
                        st_split1(g_hh, g_hl, (size_t)gr * 160 + c, hv);
                    }
                }
            }
        } else {  // EPI == 3
            float q = 0.f;
#pragma unroll
            for (int j = 0; j < NJ; j++) q += v[j] * v[j];
            float sc = 1.f / fmaxf(sqrtf(wsum(q)), 1e-12f);
            if (rv) {
#pragma unroll
                for (int j = 0; j < NJ; j++)
                    Y[(size_t)gr * ldy + lane + 32 * j] = v[j] * sc;
            }
        }
    }
}

// ================= weight / input split kernels =================
__global__ void split_w(const float* __restrict__ W, __nv_bfloat16* __restrict__ H,
                        __nv_bfloat16* __restrict__ L, int NR, int K, int KPAD) {
    int t = blockIdx.x * blockDim.x + threadIdx.x;
    if (t >= NR * KPAD) return;
    int r = t / KPAD, c = t - r * KPAD;
    float v = (c < K) ? W[r * K + c] : 0.f;
    __nv_bfloat16 h = __float2bfloat16(v);
    H[t] = h;
    L[t] = __float2bfloat16(v - __bfloat162float(h));
}
__global__ void split_msg(const float* __restrict__ wm, const float* __restrict__ bm) {
    int t = blockIdx.x * blockDim.x + threadIdx.x;
    if (t < 320 * 160) {
        int r = t / 160, c = t - r * 160;
        float v = (r < 160) ? wm[r * 320 + c] : wm[(r - 160) * 320 + 160 + c];
        __nv_bfloat16 h = __float2bfloat16(v);
        g_wmh[t] = h;
        g_wml[t] = __float2bfloat16(v - __bfloat162float(h));
    }
    if (t < 320) g_bias320[t] = (t < 160) ? bm[t] : 0.f;
}

// ================= zero / degree =================
__global__ void zero_cnt() {
    int i = blockIdx.x * blockDim.x + threadIdx.x;
    if (i < N_NODES) g_cnt[i] = 0.f;
}
__global__ void zero_msum() {
    int i = blockIdx.x * blockDim.x + threadIdx.x;
    int st = gridDim.x * blockDim.x;
    uint4* p = (uint4*)g_msum;
    const int n4 = N_NODES * 20;   // 160 halves = 20 uint4 per node
    uint4 z = make_uint4(0, 0, 0, 0);
    for (int k = i; k < n4; k += st) p[k] = z;
}
__global__ void degree_kernel(const int* __restrict__ ei) {
    int e = blockIdx.x * blockDim.x + threadIdx.x;
    if (e < N_EDGES) atomicAdd(&g_cnt[ei[N_EDGES + e]], 1.0f);
}

// ================= edge pass (fp16 gather, fp16x2 vector-reduction scatter) ========
__global__ void edge_kernel(const int* __restrict__ ei, const float* __restrict__ ew,
                            const float* __restrict__ gmv, const float* __restrict__ bemv)
{
    int w = (blockIdx.x * blockDim.x + threadIdx.x) >> 5;
    int lane = threadIdx.x & 31;
    if (w >= N_EDGES) return;
    int src = ei[w];
    int dst = ei[N_EDGES + w];
    float ewt = ew[w];
    const bool act = lane < 20;

    float v[8];
#pragma unroll
    for (int k = 0; k < 8; k++) v[k] = 0.f;
    if (act) {
        uint4 sv = *(const uint4*)(g_AB + (size_t)src * 320 + lane * 8);
        uint4 dv = *(const uint4*)(g_AB + (size_t)dst * 320 + 160 + lane * 8);
        const __half2* sh = (const __half2*)&sv;
        const __half2* dh = (const __half2*)&dv;
#pragma unroll
        for (int k = 0; k < 4; k++) {
            float2 a = __half22float2(sh[k]);
            float2 b = __half22float2(dh[k]);
            v[2 * k + 0] = a.x + b.x;
            v[2 * k + 1] = a.y + b.y;
        }
    }

    float s = 0.f;
#pragma unroll
    for (int k = 0; k < 8; k++) s += v[k];
    float mean = wsum(s) * (1.0f / 160.0f);

    float q = 0.f;
    if (act) {
#pragma unroll
        for (int k = 0; k < 8; k++) q += (v[k] - mean) * (v[k] - mean);
    }
    float var = wsum(q) * (1.0f / 160.0f);
    float rstd = rsqrtf(var + LN_EPS);

    if (act) {
        const int c0 = lane * 8;
        float4 g0 = ((const float4*)gmv)[2 * lane];
        float4 g1 = ((const float4*)gmv)[2 * lane + 1];
        float4 b0 = ((const float4*)bemv)[2 * lane];
        float4 b1 = ((const float4*)bemv)[2 * lane + 1];
        float4 o0, o1;
        o0.x = fmaxf(0.f, (v[0] - mean) * rstd * g0.x + b0.x) * ewt;
        o0.y = fmaxf(0.f, (v[1] - mean) * rstd * g0.y + b0.y) * ewt;
        o0.z = fmaxf(0.f, (v[2] - mean) * rstd * g0.z + b0.z) * ewt;
        o0.w = fmaxf(0.f, (v[3] - mean) * rstd * g0.w + b0.w) * ewt;
        o1.x = fmaxf(0.f, (v[4] - mean) * rstd * g1.x + b1.x) * ewt;
        o1.y = fmaxf(0.f, (v[5] - mean) * rstd * g1.y + b1.y) * ewt;
        o1.z = fmaxf(0.f, (v[6] - mean) * rstd * g1.z + b1.z) * ewt;
        o1.w = fmaxf(0.f, (v[7] - mean) * rstd * g1.w + b1.w) * ewt;
        red8h(g_msum + (size_t)dst * 160 + c0, o0, o1);
    }
}

// ================= node pass 1: U=[h|messages] split to bf16, gate tw =============
__global__ void node1_kernel(const float* __restrict__ wgv, const float* __restrict__ bgv) {
    int n = (blockIdx.x * blockDim.x + threadIdx.x) >> 5;
    int lane = threadIdx.x & 31;
    if (n >= N_NODES) return;

    float c = g_cnt[n];
    float inv = (c > 0.f) ? 1.f / (c + 1e-8f) : 0.f;

    const float4* H = (const float4*)(g_h + (size_t)n * 160);
    const __half* Mbase = g_msum + (size_t)n * 160;
    const bool two = lane < 8;
    const size_t ub = (size_t)n * 320;

    float dotp = 0.f;
    {
        float4 h = H[lane];
        st_split4(g_uh, g_ul, ub + 4 * lane, h);
        uint2 mraw = *(const uint2*)(Mbase + 4 * lane);
        float2 f0 = __half22float2(*(const __half2*)&mraw.x);
        float2 f1 = __half22float2(*(const __half2*)&mraw.y);
        float4 mm = make_float4(f0.x * inv, f0.y * inv, f1.x * inv, f1.y * inv);
        st_split4(g_uh, g_ul, ub + 160 + 4 * lane, mm);
        float4 wg = ((const float4*)wgv)[lane];
        dotp = h.x * wg.x + h.y * wg.y + h.z * wg.z + h.w * wg.w;
    }
    if (two) {
        float4 h = H[lane + 32];
        st_split4(g_uh, g_ul, ub + 128 + 4 * lane, h);
        uint2 mraw = *(const uint2*)(Mbase + 128 + 4 * lane);
        float2 f0 = __half22float2(*(const __half2*)&mraw.x);
        float2 f1 = __half22float2(*(const __half2*)&mraw.y);
        float4 mm = make_float4(f0.x * inv, f0.y * inv, f1.x * inv, f1.y * inv);
        st_split4(g_uh, g_ul, ub + 160 + 128 + 4 * lane, mm);
        float4 wg = ((const float4*)wgv)[lane + 32];
        dotp += h.x * wg.x + h.y * wg.y + h.z * wg.z + h.w * wg.w;
    }
    float tot = wsum(dotp);
    if (lane == 0) g_tw[n] = 1.f / (1.f + expf(-(tot + bgv[0])));
}

// ================= host orchestration =================
extern "C" void kernel_launch(void* const* d_in, const int* in_sizes, int n_in,
                              void* d_out, int out_size)
{
    const float* node_features = (const float*)d_in[0];
    const int*   edge_index    = (const int*)d_in[1];
    const float* edge_weights  = (const float*)d_in[2];
    const float* time_steps    = (const float*)d_in[3];
    const float* w_enc   = (const float*)d_in[4];
    const float* b_enc   = (const float*)d_in[5];
    const float* g_enc   = (const float*)d_in[6];
    const float* be_enc  = (const float*)d_in[7];
    const float* w_time  = (const float*)d_in[8];
    const float* b_time  = (const float*)d_in[9];
    const float* g_time  = (const float*)d_in[10];
    const float* be_time = (const float*)d_in[11];
    const float* wm  = (const float*)d_in[12];
    const float* bm  = (const float*)d_in[13];
    const float* gm  = (const float*)d_in[14];
    const float* bem = (const float*)d_in[15];
    const float* wu  = (const float*)d_in[16];
    const float* bu  = (const float*)d_in[17];
    const float* gu  = (const float*)d_in[18];
    const float* beu = (const float*)d_in[19];
    const float* wg  = (const float*)d_in[20];
    const float* bg  = (const float*)d_in[21];
    const float* w_out = (const float*)d_in[22];
    const float* b_out = (const float*)d_in[23];
    float* out = (float*)d_out;

    float *p_h, *p_tw, *p_b320;
    __nv_bfloat16 *p_ah, *p_al, *p_hh, *p_hl, *p_uh, *p_ul;
    __nv_bfloat16 *p_weh, *p_wel, *p_wmh, *p_wml, *p_wuh, *p_wul, *p_woh, *p_wol;
    cudaGetSymbolAddress((void**)&p_h, g_h);
    cudaGetSymbolAddress((void**)&p_tw, g_tw);
    cudaGetSymbolAddress((void**)&p_b320, g_bias320);
    cudaGetSymbolAddress((void**)&p_ah, g_ah);
    cudaGetSymbolAddress((void**)&p_al, g_al);
    cudaGetSymbolAddress((void**)&p_hh, g_hh);
    cudaGetSymbolAddress((void**)&p_hl, g_hl);
    cudaGetSymbolAddress((void**)&p_uh, g_uh);
    cudaGetSymbolAddress((void**)&p_ul, g_ul);
    cudaGetSymbolAddress((void**)&p_weh, g_weh);
    cudaGetSymbolAddress((void**)&p_wel, g_wel);
    cudaGetSymbolAddress((void**)&p_wmh, g_wmh);
    cudaGetSymbolAddress((void**)&p_wml, g_wml);
    cudaGetSymbolAddress((void**)&p_wuh, g_wuh);
    cudaGetSymbolAddress((void**)&p_wul, g_wul);
    cudaGetSymbolAddress((void**)&p_woh, g_woh);
    cudaGetSymbolAddress((void**)&p_wol, g_wol);

    const int GBM = (N_NODES + 63) / 64;                     // 1563 row-tiles (M64)
    const int NODE_WARP_BLOCKS = (N_NODES * 32 + 255) / 256; // 12500
    const int EDGE_WARP_BLOCKS = (N_EDGES * 32 + 255) / 256; // 100000

    const int SM160 = 16384 + 160 * 256 + 1024;   // 58368 (Dsm 40KB overlays)
    const int SM128 = 16384 + 128 * 256 + 1024;   // 50176 (Dsm 32KB overlays)
    cudaFuncSetAttribute(gemm_tc<128, 128, 1>, cudaFuncAttributeMaxDynamicSharedMemorySize, SM128);
    cudaFuncSetAttribute(gemm_tc<160, 160, 0>, cudaFuncAttributeMaxDynamicSharedMemorySize, SM160);
    cudaFuncSetAttribute(gemm_tc<160, 320, 2>, cudaFuncAttributeMaxDynamicSharedMemorySize, SM160);
    cudaFuncSetAttribute(gemm_tc<128, 160, 3>, cudaFuncAttributeMaxDynamicSharedMemorySize, SM128);

    // degrees (constant across layers)
    zero_cnt<<<(N_NODES + 255) / 256, 256>>>();
    degree_kernel<<<(N_EDGES + 255) / 256, 256>>>(edge_index);

    // split inputs/weights for encoder
    split_w<<<(N_NODES * 128 + 255) / 256, 256>>>(node_features, p_ah, p_al, N_NODES, 128, 128);
    split_w<<<(128 * 128 + 255) / 256, 256>>>(w_enc, p_weh, p_wel, 128, 128, 128);
    gemm_tc<128, 128, 1><<<dim3(1, GBM), 256, SM128>>>(
        p_ah, p_al, p_weh, p_wel, b_enc, p_h, 160,
        g_enc, be_enc, time_steps, w_time, b_time, g_time, be_time, nullptr);

    for (int l = 0; l < 2; l++) {
        split_msg<<<(320 * 160 + 255) / 256, 256>>>(wm + (size_t)l * 160 * 320, bm + l * 160);
        gemm_tc<160, 160, 0><<<dim3(2, GBM), 256, SM160>>>(
            p_hh, p_hl, p_wmh, p_wml, p_b320, nullptr, 0,
            nullptr, nullptr, nullptr, nullptr, nullptr, nullptr, nullptr, nullptr);
        zero_msum<<<4096, 256>>>();
        edge_kernel<<<EDGE_WARP_BLOCKS, 256>>>(edge_index, edge_weights, gm + l * 160, bem + l * 160);
        node1_kernel<<<NODE_WARP_BLOCKS, 256>>>(wg + l * 160, bg + l);
        split_w<<<(160 * 320 + 255) / 256, 256>>>(wu + (size_t)l * 160 * 320, p_wuh, p_wul, 160, 320, 320);
        gemm_tc<160, 320, 2><<<dim3(1, GBM), 256, SM160>>>(
            p_uh, p_ul, p_wuh, p_wul, bu + l * 160, nullptr, 0,
            gu + l * 160, beu + l * 160, p_tw, nullptr, nullptr, nullptr, nullptr, p_h);
    }

    split_w<<<(128 * 160 + 255) / 256, 256>>>(w_out, p_woh, p_wol, 128, 160, 160);
    gemm_tc<128, 160, 3><<<dim3(1, GBM), 256, SM128>>>(
        p_hh, p_hl, p_woh, p_wol, b_out, out, 128,
        nullptr, nullptr, nullptr, nullptr, nullptr, nullptr, nullptr, nullptr);
}

// round 17
// speedup vs baseline: 1.7139x; 1.0274x over previous
#include <cuda_runtime.h>
#include <cuda_bf16.h>
#include <cuda_fp16.h>
#include <math.h>
#include <stdint.h>

#define N_NODES 100000
#define NROWS_PAD 100096          // >= 1563 * 64
#define N_EDGES 800000
#define LN_EPS 1e-5f

// ================= scratch (device globals; no allocation allowed) =================
__device__ float g_h[(size_t)N_NODES * 160];      // node state fp32
__device__ __half g_AB[(size_t)NROWS_PAD * 320];  // message A|B fp16 (L2-resident)
__device__ __half g_msum[(size_t)N_NODES * 160];  // scatter-add accumulator (fp16)
__device__ float g_cnt[N_NODES];                  // in-degree
__device__ float g_tw[N_NODES];                   // gate
__device__ float g_bias320[320];                  // [bm | 0]

// bf16 hi/lo pre-split GEMM A operands
__device__ __align__(16) __nv_bfloat16 g_ah[(size_t)NROWS_PAD * 128], g_al[(size_t)NROWS_PAD * 128];   // node_features
__device__ __align__(16) __nv_bfloat16 g_hh[(size_t)NROWS_PAD * 160], g_hl[(size_t)NROWS_PAD * 160];   // h (K=160, no pad)
__device__ __align__(16) __nv_bfloat16 g_uh[(size_t)NROWS_PAD * 320], g_ul[(size_t)NROWS_PAD * 320];   // U=[h|msg]

// bf16 hi/lo split weights
__device__ __align__(16) __nv_bfloat16 g_weh[128 * 128], g_wel[128 * 128];   // encoder
__device__ __align__(16) __nv_bfloat16 g_wmh[320 * 160], g_wml[320 * 160];   // message (K=160)
__device__ __align__(16) __nv_bfloat16 g_wuh[160 * 320], g_wul[160 * 320];   // update
__device__ __align__(16) __nv_bfloat16 g_woh[128 * 160], g_wol[128 * 160];   // output (K=160)

// ================= helpers =================
__device__ __forceinline__ uint32_t smem_u32(const void* p) {
    uint32_t a;
    asm("{ .reg .u64 t; cvta.to.shared.u64 t, %1; cvt.u32.u64 %0, t; }" : "=r"(a) : "l"(p));
    return a;
}
#define SWZ128(o) ((o) ^ (((o) >> 3) & 0x70))

__device__ __forceinline__ void cpa16(uint32_t dst, const void* src) {
    asm volatile("cp.async.cg.shared.global [%0], [%1], 16;" :: "r"(dst), "l"(src));
}
#define CP_COMMIT() asm volatile("cp.async.commit_group;" ::: "memory")
#define CP_WAIT0()  asm volatile("cp.async.wait_group 0;" ::: "memory")

__device__ __forceinline__ void ldsm4(uint32_t* r, uint32_t addr) {
    asm volatile("ldmatrix.sync.aligned.m8n8.x4.shared.b16 {%0,%1,%2,%3}, [%4];"
        : "=r"(r[0]), "=r"(r[1]), "=r"(r[2]), "=r"(r[3]) : "r"(addr));
}
__device__ __forceinline__ void ldsm2(uint32_t* r, uint32_t addr) {
    asm volatile("ldmatrix.sync.aligned.m8n8.x2.shared.b16 {%0,%1}, [%2];"
        : "=r"(r[0]), "=r"(r[1]) : "r"(addr));
}
__device__ __forceinline__ void mma16816(float* d, const uint32_t* a, const uint32_t* b) {
    asm volatile("mma.sync.aligned.m16n8k16.row.col.f32.bf16.bf16.f32 "
        "{%0,%1,%2,%3},{%4,%5,%6,%7},{%8,%9},{%0,%1,%2,%3};"
        : "+f"(d[0]), "+f"(d[1]), "+f"(d[2]), "+f"(d[3])
        : "r"(a[0]), "r"(a[1]), "r"(a[2]), "r"(a[3]), "r"(b[0]), "r"(b[1]));
}
__device__ __forceinline__ void split2(float a, float b, uint32_t& hi, uint32_t& lo) {
    __nv_bfloat16 ha = __float2bfloat16(a), hb = __float2bfloat16(b);
    __nv_bfloat16 la = __float2bfloat16(a - __bfloat162float(ha));
    __nv_bfloat16 lb = __float2bfloat16(b - __bfloat162float(hb));
    hi = (uint32_t)__bfloat16_as_ushort(ha) | ((uint32_t)__bfloat16_as_ushort(hb) << 16);
    lo = (uint32_t)__bfloat16_as_ushort(la) | ((uint32_t)__bfloat16_as_ushort(lb) << 16);
}
__device__ __forceinline__ void st_split1(__nv_bfloat16* H, __nv_bfloat16* L, size_t idx, float v) {
    __nv_bfloat16 h = __float2bfloat16(v);
    H[idx] = h;
    L[idx] = __float2bfloat16(v - __bfloat162float(h));
}
__device__ __forceinline__ void st_split4(__nv_bfloat16* H, __nv_bfloat16* L, size_t idx, float4 v) {
    uint2 hp, lp;
    split2(v.x, v.y, hp.x, lp.x);
    split2(v.z, v.w, hp.y, lp.y);
    *(uint2*)(H + idx) = hp;
    *(uint2*)(L + idx) = lp;
}
__device__ __forceinline__ float wsum(float v) {
#pragma unroll
    for (int o = 16; o; o >>= 1) v += __shfl_xor_sync(0xffffffffu, v, o);
    return v;
}
// fp16x2 vector reduction: 8 half channels per op
__device__ __forceinline__ void red8h(__half* p, float4 a, float4 b) {
    __half2 h0 = __floats2half2_rn(a.x, a.y);
    __half2 h1 = __floats2half2_rn(a.z, a.w);
    __half2 h2 = __floats2half2_rn(b.x, b.y);
    __half2 h3 = __floats2half2_rn(b.z, b.w);
    asm volatile("red.global.add.noftz.v4.f16x2 [%0], {%1,%2,%3,%4};"
                 :: "l"(p),
                    "r"(*(uint32_t*)&h0), "r"(*(uint32_t*)&h1),
                    "r"(*(uint32_t*)&h2), "r"(*(uint32_t*)&h3) : "memory");
}

// ================= tensor-core GEMM (mma.sync bf16x3 split), M64 tiles, occ 3 =====
// D[64, NT] tile = X[64, KPAD] @ W[NT, KPAD]^T.  KPAD may be a 32-multiple (tail chunk
// handled via compile-time guards).  EPI:
//   0: bias + store fp16 to g_AB (+n0 col offset, stride 320)         (message precompute)
//   1: bias + LN(NT)+relu -> Y cols 0..127 (ldy) + g_hh/g_hl split; time enc col 128+lane
//   2: bias + LN(NT)+relu + gate blend into w0 + g_hh/g_hl split (node update)
//   3: bias + row L2-normalize -> Y (output projection)
template<int NT, int KPAD, int EPI>
__global__ __launch_bounds__(256, 3) void gemm_tc(
    const __nv_bfloat16* __restrict__ Xh, const __nv_bfloat16* __restrict__ Xl,
    const __nv_bfloat16* __restrict__ Wh, const __nv_bfloat16* __restrict__ Wl,
    const float* __restrict__ bias,
    float* __restrict__ Y, int ldy,
    const float* __restrict__ a0, const float* __restrict__ a1,
    const float* __restrict__ a2, const float* __restrict__ a3,
    const float* __restrict__ a4, const float* __restrict__ a5,
    const float* __restrict__ a6,
    float* __restrict__ w0)
{
    extern __shared__ __align__(16) char dsm[];
    char* base = (char*)((((uintptr_t)dsm) + 1023) & ~(uintptr_t)1023);
    const uint32_t sb = smem_u32(base);
    constexpr int A_HI = 0, A_LO = 8192, B_HI = 16384;
    constexpr int B_LO = 16384 + NT * 128;
    constexpr int NW = NT / 4;          // cols per warp (warp grid 2 x 4)
    constexpr int NTILES = NW / 8;      // 5 for NT=160, 4 for NT=128
    const int tid = threadIdx.x, wid = tid >> 5, lane = tid & 31;
    const int wm = wid & 1, wn = wid >> 1;
    const int bm0 = blockIdx.y * 64, n0 = blockIdx.x * NT;

    float acc[2][NTILES][4];
#pragma unroll
    for (int m = 0; m < 2; m++)
#pragma unroll
        for (int t = 0; t < NTILES; t++)
#pragma unroll
            for (int j = 0; j < 4; j++) acc[m][t][j] = 0.f;

    constexpr int NCHUNK = (KPAD + 63) / 64;
#pragma unroll
    for (int ch = 0; ch < NCHUNK; ch++) {
        const int c0 = ch * 64;
#pragma unroll
        for (int s = tid; s < 64 * 8; s += 256) {
            int r = s >> 3, i = s & 7;
            if (c0 + (i & 7) * 8 < KPAD) {
                uint32_t off = SWZ128((uint32_t)(r * 128 + i * 16));
                cpa16(sb + A_HI + off, Xh + (size_t)(bm0 + r) * KPAD + c0 + i * 8);
                cpa16(sb + A_LO + off, Xl + (size_t)(bm0 + r) * KPAD + c0 + i * 8);
            }
        }
        for (int s = tid; s < NT * 8; s += 256) {
            int r = s >> 3, i = s & 7;
            if (c0 + i * 8 < KPAD) {
                uint32_t off = SWZ128((uint32_t)(r * 128 + i * 16));
                cpa16(sb + B_HI + off, Wh + (size_t)(n0 + r) * KPAD + c0 + i * 8);
                cpa16(sb + B_LO + off, Wl + (size_t)(n0 + r) * KPAD + c0 + i * 8);
            }
        }
        CP_COMMIT();
        CP_WAIT0();
        __syncthreads();

#pragma unroll
        for (int ks = 0; ks < 4; ks++) {
            if (c0 + ks * 16 >= KPAD) break;
            uint32_t ah[2][4], al[2][4];
            const int arow = wm * 32 + (lane & 15);
            const int akb = ks * 32 + ((lane >> 4) << 4);
            {
                uint32_t o0 = SWZ128((uint32_t)(arow * 128 + akb));
                ldsm4(ah[0], sb + A_HI + o0);
                ldsm4(al[0], sb + A_LO + o0);
                uint32_t o1 = SWZ128((uint32_t)((arow + 16) * 128 + akb));
                ldsm4(ah[1], sb + A_HI + o1);
                ldsm4(al[1], sb + A_LO + o1);
            }
            const int q = lane >> 3;
            const int browb = wn * NW + ((q >> 1) << 3) + (lane & 7);
            const int bkb = ks * 32 + (q & 1) * 16;
#pragma unroll
            for (int nt = 0; nt + 1 < NTILES; nt += 2) {
                uint32_t bo = SWZ128((uint32_t)((browb + nt * 8) * 128 + bkb));
                uint32_t bh4[4], bl4[4];
                ldsm4(bh4, sb + B_HI + bo);
                ldsm4(bl4, sb + B_LO + bo);
                mma16816(acc[0][nt], ah[0], bh4);
                mma16816(acc[0][nt], ah[0], bl4);
                mma16816(acc[0][nt], al[0], bh4);
                mma16816(acc[1][nt], ah[1], bh4);
                mma16816(acc[1][nt], ah[1], bl4);
                mma16816(acc[1][nt], al[1], bh4);
                mma16816(acc[0][nt + 1], ah[0], bh4 + 2);
                mma16816(acc[0][nt + 1], ah[0], bl4 + 2);
                mma16816(acc[0][nt + 1], al[0], bh4 + 2);
                mma16816(acc[1][nt + 1], ah[1], bh4 + 2);
                mma16816(acc[1][nt + 1], ah[1], bl4 + 2);
                mma16816(acc[1][nt + 1], al[1], bh4 + 2);
            }
            if (NTILES & 1) {
                constexpr int ntl = NTILES - 1;
                const int browt = wn * NW + ntl * 8 + (lane & 7);
                const int bkt = ks * 32 + ((lane >> 3) & 1) * 16;
                uint32_t bo = SWZ128((uint32_t)(browt * 128 + bkt));
                uint32_t bh2[2], bl2[2];
                ldsm2(bh2, sb + B_HI + bo);
                ldsm2(bl2, sb + B_LO + bo);
                mma16816(acc[0][ntl], ah[0], bh2);
                mma16816(acc[0][ntl], ah[0], bl2);
                mma16816(acc[0][ntl], al[0], bh2);
                mma16816(acc[1][ntl], ah[1], bh2);
                mma16816(acc[1][ntl], ah[1], bl2);
                mma16816(acc[1][ntl], al[1], bh2);
            }
        }
        __syncthreads();
    }

    // ---------------- stage D in SMEM (reuse buffers), row-wise epilogue ----------
    float* Dsm = (float*)base;   // [64][NT]
#pragma unroll
    for (int mb = 0; mb < 2; mb++) {
        const int r0 = wm * 32 + mb * 16 + (lane >> 2);
        const int c0 = wn * NW + (lane & 3) * 2;
#pragma unroll
        for (int nt = 0; nt < NTILES; nt++) {
            *(float2*)&Dsm[r0 * NT + c0 + nt * 8] = make_float2(acc[mb][nt][0], acc[mb][nt][1]);
            *(float2*)&Dsm[(r0 + 8) * NT + c0 + nt * 8] = make_float2(acc[mb][nt][2], acc[mb][nt][3]);
        }
    }
    __syncthreads();

    constexpr int NJ = NT / 32;
    for (int rr = 0; rr < 8; rr++) {
        const int r = wid * 8 + rr;
        const int gr = bm0 + r;
        const bool rv = gr < N_NODES;
        float v[NJ];
#pragma unroll
        for (int j = 0; j < NJ; j++) {
            int c = lane + 32 * j;
            v[j] = Dsm[r * NT + c] + bias[(EPI == 0 ? n0 : 0) + c];
        }

        if (EPI == 0) {
            if (rv) {
#pragma unroll
                for (int j = 0; j < NJ; j++)
                    g_AB[(size_t)gr * 320 + n0 + lane + 32 * j] = __float2half(v[j]);
            }
        } else if (EPI == 1 || EPI == 2) {
            float s = 0.f, q = 0.f;
#pragma unroll
            for (int j = 0; j < NJ; j++) { s += v[j]; q += v[j] * v[j]; }
            float mean = wsum(s) * (1.f / NT);
            float var = wsum(q) * (1.f / NT) - mean * mean;
            float rstd = rsqrtf(var + LN_EPS);
            if (rv) {
                if (EPI == 1) {
#pragma unroll
                    for (int j = 0; j < NJ; j++) {
                        int c = lane + 32 * j;
                        float hv = fmaxf(0.f, (v[j] - mean) * rstd * a0[c] + a1[c]);
                        Y[(size_t)gr * ldy + c] = hv;
                        st_split1(g_hh, g_hl, (size_t)gr * 160 + c, hv);
                    }
                    float t0 = a2[gr];
                    float tv = t0 * a3[lane] + a4[lane];
                    float tm = wsum(tv) * (1.f / 32.f);
                    float td = tv - tm;
                    float tvar = wsum(td * td) * (1.f / 32.f);
                    float tr = rsqrtf(tvar + LN_EPS);
                    float to = fmaxf(0.f, td * tr * a5[lane] + a6[lane]);
                    Y[(size_t)gr * ldy + 128 + lane] = to;
                    st_split1(g_hh, g_hl, (size_t)gr * 160 + 128 + lane, to);
                } else {
                    float tw = a2[gr];
#pragma unroll
                    for (int j = 0; j < NJ; j++) {
                        int c = lane + 32 * j;
                        float hn = fmaxf(0.f, (v[j] - mean) * rstd * a0[c] + a1[c]);
                        float ho = w0[(size_t)gr * 160 + c];
                        float hv = tw * hn + (1.f - tw) * ho;
                        w0[(size_t)gr * 160 + c] = hv;
                        st_split1(g_hh, g_hl, (size_t)gr * 160 + c, hv);
                    }
                }
            }
        } else {  // EPI == 3
            float q = 0.f;
#pragma unroll
            for (int j = 0; j < NJ; j++) q += v[j] * v[j];
            float sc = 1.f / fmaxf(sqrtf(wsum(q)), 1e-12f);
            if (rv) {
#pragma unroll
                for (int j = 0; j < NJ; j++)
                    Y[(size_t)gr * ldy + lane + 32 * j] = v[j] * sc;
            }
        }
    }
}

// ================= weight / input split kernels =================
__global__ void split_w(const float* __restrict__ W, __nv_bfloat16* __restrict__ H,
                        __nv_bfloat16* __restrict__ L, int NR, int K, int KPAD) {
    int t = blockIdx.x * blockDim.x + threadIdx.x;
    if (t >= NR * KPAD) return;
    int r = t / KPAD, c = t - r * KPAD;
    float v = (c < K) ? W[r * K + c] : 0.f;
    __nv_bfloat16 h = __float2bfloat16(v);
    H[t] = h;
    L[t] = __float2bfloat16(v - __bfloat162float(h));
}
__global__ void split_msg(const float* __restrict__ wm, const float* __restrict__ bm) {
    int t = blockIdx.x * blockDim.x + threadIdx.x;
    if (t < 320 * 160) {
        int r = t / 160, c = t - r * 160;
        float v = (r < 160) ? wm[r * 320 + c] : wm[(r - 160) * 320 + 160 + c];
        __nv_bfloat16 h = __float2bfloat16(v);
        g_wmh[t] = h;
        g_wml[t] = __float2bfloat16(v - __bfloat162float(h));
    }
    if (t < 320) g_bias320[t] = (t < 160) ? bm[t] : 0.f;
}

// ================= zero / degree =================
__global__ void zero_cnt() {
    int i = blockIdx.x * blockDim.x + threadIdx.x;
    if (i < N_NODES) g_cnt[i] = 0.f;
}
__global__ void zero_msum() {
    int i = blockIdx.x * blockDim.x + threadIdx.x;
    int st = gridDim.x * blockDim.x;
    uint4* p = (uint4*)g_msum;
    const int n4 = N_NODES * 20;   // 160 halves = 20 uint4 per node
    uint4 z = make_uint4(0, 0, 0, 0);
    for (int k = i; k < n4; k += st) p[k] = z;
}
__global__ void degree_kernel(const int* __restrict__ ei) {
    int e = blockIdx.x * blockDim.x + threadIdx.x;
    if (e < N_EDGES) atomicAdd(&g_cnt[ei[N_EDGES + e]], 1.0f);
}

// ================= edge pass: TWO edges per warp (fp16 gather, fp16x2 red scatter) =
__global__ __launch_bounds__(256) void edge_kernel(
    const int* __restrict__ ei, const float* __restrict__ ew,
    const float* __restrict__ gmv, const float* __restrict__ bemv)
{
    int w = (blockIdx.x * blockDim.x + threadIdx.x) >> 5;
    int lane = threadIdx.x & 31;
    int e0 = 2 * w;
    if (e0 >= N_EDGES) return;
    const bool two = (e0 + 1) < N_EDGES;
    const bool act = lane < 20;

    int src0 = ei[e0], dst0 = ei[N_EDGES + e0];
    int src1 = two ? ei[e0 + 1] : src0;
    int dst1 = two ? ei[N_EDGES + e0 + 1] : dst0;
    float ewt0 = ew[e0];
    float ewt1 = two ? ew[e0 + 1] : 0.f;

    // LN params shared by both edges
    float gv[8], bv[8];
#pragma unroll
    for (int k = 0; k < 8; k++) { gv[k] = 0.f; bv[k] = 0.f; }
    if (act) {
        float4 g0 = ((const float4*)gmv)[2 * lane];
        float4 g1 = ((const float4*)gmv)[2 * lane + 1];
        float4 b0 = ((const float4*)bemv)[2 * lane];
        float4 b1 = ((const float4*)bemv)[2 * lane + 1];
        gv[0] = g0.x; gv[1] = g0.y; gv[2] = g0.z; gv[3] = g0.w;
        gv[4] = g1.x; gv[5] = g1.y; gv[6] = g1.z; gv[7] = g1.w;
        bv[0] = b0.x; bv[1] = b0.y; bv[2] = b0.z; bv[3] = b0.w;
        bv[4] = b1.x; bv[5] = b1.y; bv[6] = b1.z; bv[7] = b1.w;
    }

    float v0[8], v1[8];
#pragma unroll
    for (int k = 0; k < 8; k++) { v0[k] = 0.f; v1[k] = 0.f; }
    if (act) {
        uint4 sa = *(const uint4*)(g_AB + (size_t)src0 * 320 + lane * 8);
        uint4 da = *(const uint4*)(g_AB + (size_t)dst0 * 320 + 160 + lane * 8);
        uint4 sb2 = *(const uint4*)(g_AB + (size_t)src1 * 320 + lane * 8);
        uint4 db2 = *(const uint4*)(g_AB + (size_t)dst1 * 320 + 160 + lane * 8);
        const __half2* sh0 = (const __half2*)&sa;
        const __half2* dh0 = (const __half2*)&da;
        const __half2* sh1 = (const __half2*)&sb2;
        const __half2* dh1 = (const __half2*)&db2;
#pragma unroll
        for (int k = 0; k < 4; k++) {
            float2 a0f = __half22float2(sh0[k]);
            float2 b0f = __half22float2(dh0[k]);
            v0[2 * k + 0] = a0f.x + b0f.x;
            v0[2 * k + 1] = a0f.y + b0f.y;
            float2 a1f = __half22float2(sh1[k]);
            float2 b1f = __half22float2(dh1[k]);
            v1[2 * k + 0] = a1f.x + b1f.x;
            v1[2 * k + 1] = a1f.y + b1f.y;
        }
    }

    // means (two independent shfl chains, interleaved by unroll)
    float s0 = 0.f, s1 = 0.f;
#pragma unroll
    for (int k = 0; k < 8; k++) { s0 += v0[k]; s1 += v1[k]; }
#pragma unroll
    for (int o = 16; o; o >>= 1) {
        s0 += __shfl_xor_sync(0xffffffffu, s0, o);
        s1 += __shfl_xor_sync(0xffffffffu, s1, o);
    }
    float mean0 = s0 * (1.0f / 160.0f);
    float mean1 = s1 * (1.0f / 160.0f);

    float q0 = 0.f, q1 = 0.f;
    if (act) {
#pragma unroll
        for (int k = 0; k < 8; k++) {
            q0 += (v0[k] - mean0) * (v0[k] - mean0);
            q1 += (v1[k] - mean1) * (v1[k] - mean1);
        }
    }
#pragma unroll
    for (int o = 16; o; o >>= 1) {
        q0 += __shfl_xor_sync(0xffffffffu, q0, o);
        q1 += __shfl_xor_sync(0xffffffffu, q1, o);
    }
    float rstd0 = rsqrtf(q0 * (1.0f / 160.0f) + LN_EPS);
    float rstd1 = rsqrtf(q1 * (1.0f / 160.0f) + LN_EPS);

    if (act) {
        const int c0 = lane * 8;
        {
            float4 o0, o1;
            o0.x = fmaxf(0.f, (v0[0] - mean0) * rstd0 * gv[0] + bv[0]) * ewt0;
            o0.y = fmaxf(0.f, (v0[1] - mean0) * rstd0 * gv[1] + bv[1]) * ewt0;
            o0.z = fmaxf(0.f, (v0[2] - mean0) * rstd0 * gv[2] + bv[2]) * ewt0;
            o0.w = fmaxf(0.f, (v0[3] - mean0) * rstd0 * gv[3] + bv[3]) * ewt0;
            o1.x = fmaxf(0.f, (v0[4] - mean0) * rstd0 * gv[4] + bv[4]) * ewt0;
            o1.y = fmaxf(0.f, (v0[5] - mean0) * rstd0 * gv[5] + bv[5]) * ewt0;
            o1.z = fmaxf(0.f, (v0[6] - mean0) * rstd0 * gv[6] + bv[6]) * ewt0;
            o1.w = fmaxf(0.f, (v0[7] - mean0) * rstd0 * gv[7] + bv[7]) * ewt0;
            red8h(g_msum + (size_t)dst0 * 160 + c0, o0, o1);
        }
        if (two) {
            float4 o0, o1;
            o0.x = fmaxf(0.f, (v1[0] - mean1) * rstd1 * gv[0] + bv[0]) * ewt1;
            o0.y = fmaxf(0.f, (v1[1] - mean1) * rstd1 * gv[1] + bv[1]) * ewt1;
            o0.z = fmaxf(0.f, (v1[2] - mean1) * rstd1 * gv[2] + bv[2]) * ewt1;
            o0.w = fmaxf(0.f, (v1[3] - mean1) * rstd1 * gv[3] + bv[3]) * ewt1;
            o1.x = fmaxf(0.f, (v1[4] - mean1) * rstd1 * gv[4] + bv[4]) * ewt1;
            o1.y = fmaxf(0.f, (v1[5] - mean1) * rstd1 * gv[5] + bv[5]) * ewt1;
            o1.z = fmaxf(0.f, (v1[6] - mean1) * rstd1 * gv[6] + bv[6]) * ewt1;
            o1.w = fmaxf(0.f, (v1[7] - mean1) * rstd1 * gv[7] + bv[7]) * ewt1;
            red8h(g_msum + (size_t)dst1 * 160 + c0, o0, o1);
        }
    }
}

// ================= node pass 1: U=[h|messages] split to bf16, gate tw =============
__global__ void node1_kernel(const float* __restrict__ wgv, const float* __restrict__ bgv) {
    int n = (blockIdx.x * blockDim.x + threadIdx.x) >> 5;
    int lane = threadIdx.x & 31;
    if (n >= N_NODES) return;

    float c = g_cnt[n];
    float inv = (c > 0.f) ? 1.f / (c + 1e-8f) : 0.f;

    const float4* H = (const float4*)(g_h + (size_t)n * 160);
    const __half* Mbase = g_msum + (size_t)n * 160;
    const bool two = lane < 8;
    const size_t ub = (size_t)n * 320;

    float dotp = 0.f;
    {
        float4 h = H[lane];
        st_split4(g_uh, g_ul, ub + 4 * lane, h);
        uint2 mraw = *(const uint2*)(Mbase + 4 * lane);
        float2 f0 = __half22float2(*(const __half2*)&mraw.x);
        float2 f1 = __half22float2(*(const __half2*)&mraw.y);
        float4 mm = make_float4(f0.x * inv, f0.y * inv, f1.x * inv, f1.y * inv);
        st_split4(g_uh, g_ul, ub + 160 + 4 * lane, mm);
        float4 wg = ((const float4*)wgv)[lane];
        dotp = h.x * wg.x + h.y * wg.y + h.z * wg.z + h.w * wg.w;
    }
    if (two) {
        float4 h = H[lane + 32];
        st_split4(g_uh, g_ul, ub + 128 + 4 * lane, h);
        uint2 mraw = *(const uint2*)(Mbase + 128 + 4 * lane);
        float2 f0 = __half22float2(*(const __half2*)&mraw.x);
        float2 f1 = __half22float2(*(const __half2*)&mraw.y);
        float4 mm = make_float4(f0.x * inv, f0.y * inv, f1.x * inv, f1.y * inv);
        st_split4(g_uh, g_ul, ub + 160 + 128 + 4 * lane, mm);
        float4 wg = ((const float4*)wgv)[lane + 32];
        dotp += h.x * wg.x + h.y * wg.y + h.z * wg.z + h.w * wg.w;
    }
    float tot = wsum(dotp);
    if (lane == 0) g_tw[n] = 1.f / (1.f + expf(-(tot + bgv[0])));
}

// ================= host orchestration =================
extern "C" void kernel_launch(void* const* d_in, const int* in_sizes, int n_in,
                              void* d_out, int out_size)
{
    const float* node_features = (const float*)d_in[0];
    const int*   edge_index    = (const int*)d_in[1];
    const float* edge_weights  = (const float*)d_in[2];
    const float* time_steps    = (const float*)d_in[3];
    const float* w_enc   = (const float*)d_in[4];
    const float* b_enc   = (const float*)d_in[5];
    const float* g_enc   = (const float*)d_in[6];
    const float* be_enc  = (const float*)d_in[7];
    const float* w_time  = (const float*)d_in[8];
    const float* b_time  = (const float*)d_in[9];
    const float* g_time  = (const float*)d_in[10];
    const float* be_time = (const float*)d_in[11];
    const float* wm  = (const float*)d_in[12];
    const float* bm  = (const float*)d_in[13];
    const float* gm  = (const float*)d_in[14];
    const float* bem = (const float*)d_in[15];
    const float* wu  = (const float*)d_in[16];
    const float* bu  = (const float*)d_in[17];
    const float* gu  = (const float*)d_in[18];
    const float* beu = (const float*)d_in[19];
    const float* wg  = (const float*)d_in[20];
    const float* bg  = (const float*)d_in[21];
    const float* w_out = (const float*)d_in[22];
    const float* b_out = (const float*)d_in[23];
    float* out = (float*)d_out;

    float *p_h, *p_tw, *p_b320;
    __nv_bfloat16 *p_ah, *p_al, *p_hh, *p_hl, *p_uh, *p_ul;
    __nv_bfloat16 *p_weh, *p_wel, *p_wmh, *p_wml, *p_wuh, *p_wul, *p_woh, *p_wol;
    cudaGetSymbolAddress((void**)&p_h, g_h);
    cudaGetSymbolAddress((void**)&p_tw, g_tw);
    cudaGetSymbolAddress((void**)&p_b320, g_bias320);
    cudaGetSymbolAddress((void**)&p_ah, g_ah);
    cudaGetSymbolAddress((void**)&p_al, g_al);
    cudaGetSymbolAddress((void**)&p_hh, g_hh);
    cudaGetSymbolAddress((void**)&p_hl, g_hl);
    cudaGetSymbolAddress((void**)&p_uh, g_uh);
    cudaGetSymbolAddress((void**)&p_ul, g_ul);
    cudaGetSymbolAddress((void**)&p_weh, g_weh);
    cudaGetSymbolAddress((void**)&p_wel, g_wel);
    cudaGetSymbolAddress((void**)&p_wmh, g_wmh);
    cudaGetSymbolAddress((void**)&p_wml, g_wml);
    cudaGetSymbolAddress((void**)&p_wuh, g_wuh);
    cudaGetSymbolAddress((void**)&p_wul, g_wul);
    cudaGetSymbolAddress((void**)&p_woh, g_woh);
    cudaGetSymbolAddress((void**)&p_wol, g_wol);

    const int GBM = (N_NODES + 63) / 64;                     // 1563 row-tiles (M64)
    const int NODE_WARP_BLOCKS = (N_NODES * 32 + 255) / 256; // 12500
    const int EDGE_WARP_BLOCKS = ((N_EDGES / 2) * 32 + 255) / 256; // 50000 (2 edges/warp)

    const int SM160 = 16384 + 160 * 256 + 1024;   // 58368 (Dsm 40KB overlays)
    const int SM128 = 16384 + 128 * 256 + 1024;   // 50176 (Dsm 32KB overlays)
    cudaFuncSetAttribute(gemm_tc<128, 128, 1>, cudaFuncAttributeMaxDynamicSharedMemorySize, SM128);
    cudaFuncSetAttribute(gemm_tc<160, 160, 0>, cudaFuncAttributeMaxDynamicSharedMemorySize, SM160);
    cudaFuncSetAttribute(gemm_tc<160, 320, 2>, cudaFuncAttributeMaxDynamicSharedMemorySize, SM160);
    cudaFuncSetAttribute(gemm_tc<128, 160, 3>, cudaFuncAttributeMaxDynamicSharedMemorySize, SM128);

    // degrees (constant across layers)
    zero_cnt<<<(N_NODES + 255) / 256, 256>>>();
    degree_kernel<<<(N_EDGES + 255) / 256, 256>>>(edge_index);

    // split inputs/weights for encoder
    split_w<<<(N_NODES * 128 + 255) / 256, 256>>>(node_features, p_ah, p_al, N_NODES, 128, 128);
    split_w<<<(128 * 128 + 255) / 256, 256>>>(w_enc, p_weh, p_wel, 128, 128, 128);
    gemm_tc<128, 128, 1><<<dim3(1, GBM), 256, SM128>>>(
        p_ah, p_al, p_weh, p_wel, b_enc, p_h, 160,
        g_enc, be_enc, time_steps, w_time, b_time, g_time, be_time, nullptr);

    for (int l = 0; l < 2; l++) {
        split_msg<<<(320 * 160 + 255) / 256, 256>>>(wm + (size_t)l * 160 * 320, bm + l * 160);
        gemm_tc<160, 160, 0><<<dim3(2, GBM), 256, SM160>>>(
            p_hh, p_hl, p_wmh, p_wml, p_b320, nullptr, 0,
            nullptr, nullptr, nullptr, nullptr, nullptr, nullptr, nullptr, nullptr);
        zero_msum<<<4096, 256>>>();
        edge_kernel<<<EDGE_WARP_BLOCKS, 256>>>(edge_index, edge_weights, gm + l * 160, bem + l * 160);
        node1_kernel<<<NODE_WARP_BLOCKS, 256>>>(wg + l * 160, bg + l);
        split_w<<<(160 * 320 + 255) / 256, 256>>>(wu + (size_t)l * 160 * 320, p_wuh, p_wul, 160, 320, 320);
        gemm_tc<160, 320, 2><<<dim3(1, GBM), 256, SM160>>>(
            p_uh, p_ul, p_wuh, p_wul, bu + l * 160, nullptr, 0,
            gu + l * 160, beu + l * 160, p_tw, nullptr, nullptr, nullptr, nullptr, p_h);
    }

    split_w<<<(128 * 160 + 255) / 256, 256>>>(w_out, p_woh, p_wol, 128, 160, 160);
    gemm_tc<128, 160, 3><<<dim3(1, GBM), 256, SM128>>>(
        p_hh, p_hl, p_woh, p_wol, b_out, out, 128,
        nullptr, nullptr, nullptr, nullptr, nullptr, nullptr, nullptr, nullptr);
}